// round 6
// baseline (speedup 1.0000x reference)
#include <cuda_runtime.h>
#include <cuda_bf16.h>
#include <math.h>
#include <float.h>

// ---------------- problem constants (fixed dataset) ----------------
#define NPTS    20000
#define PD      64          // point feature dim
#define GD      256         // grid feature dim
#define HH      96
#define WW      96
#define G       (HH*WW)     // 9216 grid points
#define KNN     32
#define HID     64
#define NC      64          // bin grid 64x64
#define NCELLS  (NC*NC)
#define CAP     1024        // candidate capacity per grid point
#define EPSLN   1e-5f

// step = f32(1/95), exactly as JAX f32 linspace computes it
#define STEP    (1.0f/95.0f)

// ---------------- scratch (device globals, no allocations) ----------------
__device__ float  g_pf[NPTS*GD];       // projected point features (20.5 MB)
__device__ int    g_start[NCELLS+1];
__device__ float4 g_pts[NPTS];         // (px, py, p2, idx-as-float), binned order
__device__ int    g_knn[G*KNN];
__device__ float  g_mid[G*GD];         // aggregated features before out-proj

// exact-rounding helpers for the KNN distance path (must bit-match reference)
__device__ __forceinline__ float grid_coord(int i) {
    return __fmul_rn((float)i, STEP);
}
__device__ __forceinline__ float sum_sq(float x, float y) {
    return __fadd_rn(__fmul_rn(x, x), __fmul_rn(y, y));
}
__device__ __forceinline__ float dot_ref(float gx, float gy, float px, float py) {
    return __fadd_rn(__fmul_rn(gx, px), __fmul_rn(gy, py));
}
__device__ __forceinline__ float dist2_ref(float g2, float m, float p2) {
    return __fadd_rn(__fsub_rn(g2, __fmul_rn(2.0f, m)), p2);
}
__device__ __forceinline__ int cell_of(float px, float py) {
    int cx = (int)(px * NC); cx = min(max(cx, 0), NC-1);
    int cy = (int)(py * NC); cy = min(max(cy, 0), NC-1);
    return cy * NC + cx;
}

// ======================================================================
// Kernel 1: pf = feat @ W_feat^T + b_feat   [20000 x 256]
// 32 rows x 256 cols per block; 256 threads; thread tile 8 rows x 4 cols.
// ======================================================================
__global__ __launch_bounds__(256) void pf_kernel(
    const float* __restrict__ feat,   // [NPTS,64]
    const float* __restrict__ Wf,     // [256,64]
    const float* __restrict__ bf)     // [256]
{
    __shared__ __align__(16) float sW[32*260];   // [kk][c]
    __shared__ __align__(16) float sF[32*36];    // [kk][r]
    const int t    = threadIdx.x;
    const int row0 = blockIdx.x * 32;
    const int ty   = t >> 6;           // 0..3 -> r0 = ty*8
    const int tx   = t & 63;           // c0 = tx*4
    const int r0   = ty * 8;
    const int c0   = tx * 4;

    const float4* feat4 = (const float4*)feat;   // row stride 16
    const float4* Wf4   = (const float4*)Wf;     // row stride 16

    float4 acc[8];
#pragma unroll
    for (int r = 0; r < 8; r++) acc[r] = make_float4(0.f,0.f,0.f,0.f);

    for (int kt = 0; kt < PD; kt += 32) {
#pragma unroll
        for (int i = 0; i < 8; i++) {
            int lin = i * 256 + t;          // 0..2047
            int kk4 = lin & 7;              // kk = kk4*4
            int c   = lin >> 3;             // 0..255
            float4 v = Wf4[c*16 + (kt>>2) + kk4];
            sW[(kk4*4+0)*260 + c] = v.x;
            sW[(kk4*4+1)*260 + c] = v.y;
            sW[(kk4*4+2)*260 + c] = v.z;
            sW[(kk4*4+3)*260 + c] = v.w;
        }
        {
            int kk4 = t & 7;
            int r   = t >> 3;               // 0..31
            float4 v = feat4[(size_t)(row0 + r)*16 + (kt>>2) + kk4];
            sF[(kk4*4+0)*36 + r] = v.x;
            sF[(kk4*4+1)*36 + r] = v.y;
            sF[(kk4*4+2)*36 + r] = v.z;
            sF[(kk4*4+3)*36 + r] = v.w;
        }
        __syncthreads();
#pragma unroll
        for (int kk = 0; kk < 32; kk++) {
            float4 w  = *(const float4*)&sW[kk*260 + c0];
            float4 fA = *(const float4*)&sF[kk*36 + r0];
            float4 fB = *(const float4*)&sF[kk*36 + r0 + 4];
            acc[0].x = fmaf(fA.x, w.x, acc[0].x); acc[0].y = fmaf(fA.x, w.y, acc[0].y);
            acc[0].z = fmaf(fA.x, w.z, acc[0].z); acc[0].w = fmaf(fA.x, w.w, acc[0].w);
            acc[1].x = fmaf(fA.y, w.x, acc[1].x); acc[1].y = fmaf(fA.y, w.y, acc[1].y);
            acc[1].z = fmaf(fA.y, w.z, acc[1].z); acc[1].w = fmaf(fA.y, w.w, acc[1].w);
            acc[2].x = fmaf(fA.z, w.x, acc[2].x); acc[2].y = fmaf(fA.z, w.y, acc[2].y);
            acc[2].z = fmaf(fA.z, w.z, acc[2].z); acc[2].w = fmaf(fA.z, w.w, acc[2].w);
            acc[3].x = fmaf(fA.w, w.x, acc[3].x); acc[3].y = fmaf(fA.w, w.y, acc[3].y);
            acc[3].z = fmaf(fA.w, w.z, acc[3].z); acc[3].w = fmaf(fA.w, w.w, acc[3].w);
            acc[4].x = fmaf(fB.x, w.x, acc[4].x); acc[4].y = fmaf(fB.x, w.y, acc[4].y);
            acc[4].z = fmaf(fB.x, w.z, acc[4].z); acc[4].w = fmaf(fB.x, w.w, acc[4].w);
            acc[5].x = fmaf(fB.y, w.x, acc[5].x); acc[5].y = fmaf(fB.y, w.y, acc[5].y);
            acc[5].z = fmaf(fB.y, w.z, acc[5].z); acc[5].w = fmaf(fB.y, w.w, acc[5].w);
            acc[6].x = fmaf(fB.z, w.x, acc[6].x); acc[6].y = fmaf(fB.z, w.y, acc[6].y);
            acc[6].z = fmaf(fB.z, w.z, acc[6].z); acc[6].w = fmaf(fB.z, w.w, acc[6].w);
            acc[7].x = fmaf(fB.w, w.x, acc[7].x); acc[7].y = fmaf(fB.w, w.y, acc[7].y);
            acc[7].z = fmaf(fB.w, w.z, acc[7].z); acc[7].w = fmaf(fB.w, w.w, acc[7].w);
        }
        __syncthreads();
    }
    float4 b4 = *(const float4*)&bf[c0];
    float4* out4 = (float4*)g_pf;
#pragma unroll
    for (int r = 0; r < 8; r++) {
        float4 v = acc[r];
        v.x += b4.x; v.y += b4.y; v.z += b4.z; v.w += b4.w;
        out4[(size_t)(row0 + r0 + r)*64 + tx] = v;
    }
}

// ======================================================================
// Fused binning: count -> scan -> scatter, ONE block, smem counters.
// ======================================================================
__global__ __launch_bounds__(1024) void bin_all_kernel(const float* __restrict__ pc)
{
    __shared__ int scnt[NCELLS];   // 16 KB
    __shared__ int wsum[32];
    const int t = threadIdx.x;
    const float2* __restrict__ pc2 = (const float2*)pc;

    for (int i = t; i < NCELLS; i += 1024) scnt[i] = 0;
    __syncthreads();

    for (int n = t; n < NPTS; n += 1024) {
        float2 p = pc2[n];
        atomicAdd(&scnt[cell_of(p.x, p.y)], 1);
    }
    __syncthreads();

    int v[4], s = 0;
#pragma unroll
    for (int i = 0; i < 4; i++) { v[i] = scnt[t*4 + i]; s += v[i]; }
    const int lane = t & 31, wid = t >> 5;
    int incl = s;
#pragma unroll
    for (int o = 1; o < 32; o <<= 1) {
        int u = __shfl_up_sync(0xffffffffu, incl, o);
        if (lane >= o) incl += u;
    }
    if (lane == 31) wsum[wid] = incl;
    __syncthreads();
    if (wid == 0) {
        int ws = wsum[lane];
#pragma unroll
        for (int o = 1; o < 32; o <<= 1) {
            int u = __shfl_up_sync(0xffffffffu, ws, o);
            if (lane >= o) ws += u;
        }
        wsum[lane] = ws;
    }
    __syncthreads();
    int run = (wid > 0 ? wsum[wid-1] : 0) + incl - s;
    int starts[4];
#pragma unroll
    for (int i = 0; i < 4; i++) {
        starts[i] = run;
        g_start[t*4 + i] = run;
        run += v[i];
    }
    if (t == 1023) g_start[NCELLS] = run;
    __syncthreads();
#pragma unroll
    for (int i = 0; i < 4; i++) scnt[t*4 + i] = starts[i];
    __syncthreads();

    for (int n = t; n < NPTS; n += 1024) {
        float2 p = pc2[n];
        int pos = atomicAdd(&scnt[cell_of(p.x, p.y)], 1);
        g_pts[pos] = make_float4(p.x, p.y, sum_sq(p.x, p.y), __int_as_float(n));
    }
}

// ======================================================================
// Kernel: exact KNN (K=32), one block (128 threads) per grid point.
// Bit-exact dist2; bitonic sort by (dist2, idx).
// ======================================================================
__global__ __launch_bounds__(128) void knn_kernel()
{
    __shared__ float s_d[CAP];
    __shared__ int   s_i[CAP];
    __shared__ int   s_cnt;

    const int g   = blockIdx.x;
    const int tid = threadIdx.x;
    const int wx = g % WW, hy = g / WW;
    const float gx = grid_coord(wx), gy = grid_coord(hy);
    const float g2 = sum_sq(gx, gy);

    float R2 = 0.0015f;
    int cnt = 0;
    for (int iter = 0; iter < 24; iter++) {
        if (tid == 0) s_cnt = 0;
        __syncthreads();
        float R = sqrtf(R2);
        int cx0 = max(0,    (int)floorf((gx - R) * NC));
        int cx1 = min(NC-1, (int)floorf((gx + R) * NC));
        int cy0 = max(0,    (int)floorf((gy - R) * NC));
        int cy1 = min(NC-1, (int)floorf((gy + R) * NC));
        for (int cy = cy0; cy <= cy1; cy++) {
            int b = g_start[cy*NC + cx0];
            int e = g_start[cy*NC + cx1 + 1];
            for (int j = b + tid; j < e; j += 128) {
                float4 p = g_pts[j];
                float m = dot_ref(gx, gy, p.x, p.y);
                float d = dist2_ref(g2, m, p.z);
                if (d <= R2) {
                    int pos = atomicAdd(&s_cnt, 1);
                    if (pos < CAP) { s_d[pos] = d; s_i[pos] = __float_as_int(p.w); }
                }
            }
        }
        __syncthreads();
        cnt = s_cnt;
        if (cnt >= KNN && cnt <= CAP) break;
        R2 = (cnt < KNN) ? R2 * 2.0f : R2 * 0.5f;
        __syncthreads();
    }

    int M = KNN;
    while (M < cnt) M <<= 1;
    for (int j = cnt + tid; j < M; j += 128) { s_d[j] = FLT_MAX; s_i[j] = 0x7fffffff; }
    __syncthreads();

    for (int len = 2; len <= M; len <<= 1) {
        for (int stride = len >> 1; stride > 0; stride >>= 1) {
            for (int j = tid; j < (M >> 1); j += 128) {
                int i  = 2*j - (j & (stride - 1));
                int ip = i + stride;
                float d1 = s_d[i], d2 = s_d[ip];
                int   i1 = s_i[i], i2 = s_i[ip];
                bool up = ((i & len) == 0);
                bool gt = (d1 > d2) || (d1 == d2 && i1 > i2);
                bool lt = (d1 < d2) || (d1 == d2 && i1 < i2);
                if (up ? gt : lt) {
                    s_d[i] = d2; s_d[ip] = d1;
                    s_i[i] = i2; s_i[ip] = i1;
                }
            }
            __syncthreads();
        }
    }
    if (tid < KNN) g_knn[g*KNN + tid] = s_i[tid];
}

// ======================================================================
// Kernel: attention MLP + softmax + weighted feature gather
// One block (256 threads) per grid point.
// Gather: R4-proven scalar pattern (thread = column, coalesced LDG.32,
// loads front-batched by ptxas) — the R5 float4 chain serialized loads.
// ======================================================================
__global__ __launch_bounds__(256) void attn_gather_kernel(
    const float* __restrict__ pc,
    const float* __restrict__ W1, const float* __restrict__ b1,
    const float* __restrict__ W2, const float* __restrict__ b2)
{
    __shared__ int    soff[KNN];           // row offsets into g_pf
    __shared__ float  sdx[KNN], sdy[KNN], sdd[KNN];
    __shared__ float  slog[KNN], swt[KNN];
    __shared__ __align__(16) float4 sW14[HID];   // (w0,w1,w2,b1)
    __shared__ float  sW2[HID];

    const int g = blockIdx.x;
    const int t = threadIdx.x;
    const int wx = g % WW, hy = g / WW;
    const float gx = grid_coord(wx), gy = grid_coord(hy);

    if (t < HID) {
        sW14[t] = make_float4(W1[t*3], W1[t*3+1], W1[t*3+2], b1[t]);
        sW2[t]  = W2[t];
    }
    if (t < KNN) {
        int id = g_knn[g*KNN + t];
        soff[t] = id * GD;
        float px = pc[2*id], py = pc[2*id+1];
        float dx = __fsub_rn(gx, px), dy = __fsub_rn(gy, py);
        sdx[t] = dx; sdy[t] = dy;
        sdd[t] = sqrtf(sum_sq(dx, dy));
    }
    __syncthreads();

    // MLP: thread t handles neighbor k = t/8, hidden slice of 8
    {
        int k  = t >> 3;
        int j0 = (t & 7) * 8;
        float dx = sdx[k], dy = sdy[k], dd = sdd[k];
        float acc = 0.0f;
#pragma unroll
        for (int jj = 0; jj < 8; jj++) {
            int j = j0 + jj;
            float4 w = sW14[j];
            float pre = fmaf(w.x, dx, fmaf(w.y, dy, fmaf(w.z, dd, w.w)));
            float ge  = 0.5f * pre * (1.0f + erff(pre * 0.70710678118654752f));
            acc = fmaf(sW2[j], ge, acc);
        }
#pragma unroll
        for (int o = 4; o >= 1; o >>= 1)
            acc += __shfl_down_sync(0xffffffffu, acc, o, 8);
        if ((t & 7) == 0) slog[k] = acc + b2[0];
    }
    __syncthreads();

    // softmax over 32 neighbors (warp 0)
    if (t < 32) {
        float l = slog[t];
        float m = l;
#pragma unroll
        for (int o = 16; o >= 1; o >>= 1) m = fmaxf(m, __shfl_xor_sync(0xffffffffu, m, o));
        float e = expf(l - m);
        float s = e;
#pragma unroll
        for (int o = 16; o >= 1; o >>= 1) s += __shfl_xor_sync(0xffffffffu, s, o);
        swt[t] = e / s;
    }
    __syncthreads();

    // weighted gather: column c = t (coalesced scalar loads, high MLP)
    float acc = 0.0f;
#pragma unroll 8
    for (int k = 0; k < KNN; k++)
        acc = fmaf(swt[k], g_pf[(size_t)soff[k] + t], acc);
    g_mid[(size_t)g*GD + t] = acc;
}

// ======================================================================
// Kernel: out = mid @ W_out^T + b_out, then LayerNorm.
// 32 rows x 256 cols per block; thread tile 8r x 4c; LDS.128 inner loop.
// ======================================================================
__global__ __launch_bounds__(256) void outproj_ln_kernel(
    const float* __restrict__ Wo,   // [256,256]
    const float* __restrict__ bo,
    const float* __restrict__ lng,
    const float* __restrict__ lnb,
    float* __restrict__ out)
{
    __shared__ __align__(16) float sW[32*260];   // [kk][c]; reused as sOut [r][c]
    __shared__ __align__(16) float sF[32*36];    // [kk][r]
    __shared__ float sMu[32], sRs[32];

    const int t    = threadIdx.x;
    const int row0 = blockIdx.x * 32;
    const int ty   = t >> 6;
    const int tx   = t & 63;
    const int r0   = ty * 8;
    const int c0   = tx * 4;

    const float4* Wo4  = (const float4*)Wo;    // row stride 64
    const float4* mid4 = (const float4*)g_mid; // row stride 64

    float4 acc[8];
#pragma unroll
    for (int r = 0; r < 8; r++) acc[r] = make_float4(0.f,0.f,0.f,0.f);

    for (int kt = 0; kt < GD; kt += 32) {
#pragma unroll
        for (int i = 0; i < 8; i++) {
            int lin = i * 256 + t;
            int kk4 = lin & 7;
            int c   = lin >> 3;
            float4 v = Wo4[c*64 + (kt>>2) + kk4];
            sW[(kk4*4+0)*260 + c] = v.x;
            sW[(kk4*4+1)*260 + c] = v.y;
            sW[(kk4*4+2)*260 + c] = v.z;
            sW[(kk4*4+3)*260 + c] = v.w;
        }
        {
            int kk4 = t & 7;
            int r   = t >> 3;
            float4 v = mid4[(size_t)(row0 + r)*64 + (kt>>2) + kk4];
            sF[(kk4*4+0)*36 + r] = v.x;
            sF[(kk4*4+1)*36 + r] = v.y;
            sF[(kk4*4+2)*36 + r] = v.z;
            sF[(kk4*4+3)*36 + r] = v.w;
        }
        __syncthreads();
#pragma unroll
        for (int kk = 0; kk < 32; kk++) {
            float4 w  = *(const float4*)&sW[kk*260 + c0];
            float4 fA = *(const float4*)&sF[kk*36 + r0];
            float4 fB = *(const float4*)&sF[kk*36 + r0 + 4];
            acc[0].x = fmaf(fA.x, w.x, acc[0].x); acc[0].y = fmaf(fA.x, w.y, acc[0].y);
            acc[0].z = fmaf(fA.x, w.z, acc[0].z); acc[0].w = fmaf(fA.x, w.w, acc[0].w);
            acc[1].x = fmaf(fA.y, w.x, acc[1].x); acc[1].y = fmaf(fA.y, w.y, acc[1].y);
            acc[1].z = fmaf(fA.y, w.z, acc[1].z); acc[1].w = fmaf(fA.y, w.w, acc[1].w);
            acc[2].x = fmaf(fA.z, w.x, acc[2].x); acc[2].y = fmaf(fA.z, w.y, acc[2].y);
            acc[2].z = fmaf(fA.z, w.z, acc[2].z); acc[2].w = fmaf(fA.z, w.w, acc[2].w);
            acc[3].x = fmaf(fA.w, w.x, acc[3].x); acc[3].y = fmaf(fA.w, w.y, acc[3].y);
            acc[3].z = fmaf(fA.w, w.z, acc[3].z); acc[3].w = fmaf(fA.w, w.w, acc[3].w);
            acc[4].x = fmaf(fB.x, w.x, acc[4].x); acc[4].y = fmaf(fB.x, w.y, acc[4].y);
            acc[4].z = fmaf(fB.x, w.z, acc[4].z); acc[4].w = fmaf(fB.x, w.w, acc[4].w);
            acc[5].x = fmaf(fB.y, w.x, acc[5].x); acc[5].y = fmaf(fB.y, w.y, acc[5].y);
            acc[5].z = fmaf(fB.y, w.z, acc[5].z); acc[5].w = fmaf(fB.y, w.w, acc[5].w);
            acc[6].x = fmaf(fB.z, w.x, acc[6].x); acc[6].y = fmaf(fB.z, w.y, acc[6].y);
            acc[6].z = fmaf(fB.z, w.z, acc[6].z); acc[6].w = fmaf(fB.z, w.w, acc[6].w);
            acc[7].x = fmaf(fB.w, w.x, acc[7].x); acc[7].y = fmaf(fB.w, w.y, acc[7].y);
            acc[7].z = fmaf(fB.w, w.z, acc[7].z); acc[7].w = fmaf(fB.w, w.w, acc[7].w);
        }
        __syncthreads();
    }

    float4 b4 = *(const float4*)&bo[c0];
#pragma unroll
    for (int r = 0; r < 8; r++) {
        float4 v = acc[r];
        v.x += b4.x; v.y += b4.y; v.z += b4.z; v.w += b4.w;
        *(float4*)&sW[(r0 + r)*260 + c0] = v;
    }
    __syncthreads();

    const int lane = t & 31, wid = t >> 5;
    for (int r = wid; r < 32; r += 8) {
        float s = 0.0f;
#pragma unroll
        for (int i = lane; i < GD; i += 32) s += sW[r*260 + i];
#pragma unroll
        for (int o = 16; o >= 1; o >>= 1) s += __shfl_xor_sync(0xffffffffu, s, o);
        float mu = s * (1.0f / GD);
        float v = 0.0f;
#pragma unroll
        for (int i = lane; i < GD; i += 32) {
            float d = sW[r*260 + i] - mu;
            v = fmaf(d, d, v);
        }
#pragma unroll
        for (int o = 16; o >= 1; o >>= 1) v += __shfl_xor_sync(0xffffffffu, v, o);
        if (lane == 0) { sMu[r] = mu; sRs[r] = rsqrtf(v * (1.0f / GD) + EPSLN); }
    }
    __syncthreads();

    float4 g4 = *(const float4*)&lng[c0];
    float4 be4 = *(const float4*)&lnb[c0];
    float4* out4 = (float4*)out;
#pragma unroll
    for (int r = 0; r < 8; r++) {
        int rr = r0 + r;
        float mu = sMu[rr], rs = sRs[rr];
        float4 v = *(const float4*)&sW[rr*260 + c0];
        v.x = (v.x - mu) * rs * g4.x + be4.x;
        v.y = (v.y - mu) * rs * g4.y + be4.y;
        v.z = (v.z - mu) * rs * g4.z + be4.z;
        v.w = (v.w - mu) * rs * g4.w + be4.w;
        out4[(size_t)(row0 + rr)*64 + tx] = v;
    }
}

// ======================================================================
// launcher
// ======================================================================
extern "C" void kernel_launch(void* const* d_in, const int* in_sizes, int n_in,
                              void* d_out, int out_size)
{
    const float* point_features = (const float*)d_in[0];
    const float* point_coords   = (const float*)d_in[1];
    const float* W_feat         = (const float*)d_in[2];
    const float* b_feat         = (const float*)d_in[3];
    const float* W1             = (const float*)d_in[4];
    const float* b1             = (const float*)d_in[5];
    const float* W2             = (const float*)d_in[6];
    const float* b2             = (const float*)d_in[7];
    const float* W_out          = (const float*)d_in[8];
    const float* b_out          = (const float*)d_in[9];
    const float* ln_g           = (const float*)d_in[10];
    const float* ln_b           = (const float*)d_in[11];
    float* out = (float*)d_out;

    // 1. fused binning
    bin_all_kernel<<<1, 1024>>>(point_coords);

    // 2. feature projection
    pf_kernel<<<NPTS/32, 256>>>(point_features, W_feat, b_feat);

    // 3. exact KNN
    knn_kernel<<<G, 128>>>();

    // 4. attention + gather
    attn_gather_kernel<<<G, 256>>>(point_coords, W1, b1, W2, b2);

    // 5. output projection + layernorm
    outproj_ln_kernel<<<G/32, 256>>>(W_out, b_out, ln_g, ln_b, out);
}

// round 7
// speedup vs baseline: 1.2185x; 1.2185x over previous
#include <cuda_runtime.h>
#include <cuda_bf16.h>
#include <math.h>
#include <float.h>

// ---------------- problem constants (fixed dataset) ----------------
#define NPTS    20000
#define PD      64          // point feature dim
#define GD      256         // grid feature dim
#define HH      96
#define WW      96
#define G       (HH*WW)     // 9216 grid points
#define KNN     32
#define HID     64
#define NC      64          // bin grid 64x64
#define NCELLS  (NC*NC)
#define CAP     1024        // candidate capacity per grid point
#define EPSLN   1e-5f
#define GPB     8           // grid points per attn block (8 warps)

// step = f32(1/95), exactly as JAX f32 linspace computes it
#define STEP    (1.0f/95.0f)

// ---------------- scratch (device globals, no allocations) ----------------
__device__ float  g_pf[NPTS*GD];       // projected point features (20.5 MB)
__device__ int    g_start[NCELLS+1];
__device__ float4 g_pts[NPTS];         // (px, py, p2, idx-as-float), binned order
__device__ int    g_knn[G*KNN];
__device__ float  g_mid[G*GD];         // aggregated features before out-proj

// exact-rounding helpers for the KNN distance path (must bit-match reference)
__device__ __forceinline__ float grid_coord(int i) {
    return __fmul_rn((float)i, STEP);
}
__device__ __forceinline__ float sum_sq(float x, float y) {
    return __fadd_rn(__fmul_rn(x, x), __fmul_rn(y, y));
}
__device__ __forceinline__ float dot_ref(float gx, float gy, float px, float py) {
    return __fadd_rn(__fmul_rn(gx, px), __fmul_rn(gy, py));
}
__device__ __forceinline__ float dist2_ref(float g2, float m, float p2) {
    return __fadd_rn(__fsub_rn(g2, __fmul_rn(2.0f, m)), p2);
}
__device__ __forceinline__ int cell_of(float px, float py) {
    int cx = (int)(px * NC); cx = min(max(cx, 0), NC-1);
    int cy = (int)(py * NC); cy = min(max(cy, 0), NC-1);
    return cy * NC + cx;
}

// ======================================================================
// Kernel 1: pf = point_features @ W_feat^T + b_feat   [20000 x 256]
// R3-proven version: 16 rows per block, 256 threads.
// ======================================================================
__global__ __launch_bounds__(256) void pf_kernel(
    const float* __restrict__ feat,   // [NPTS,64]
    const float* __restrict__ Wf,     // [256,64]
    const float* __restrict__ bf)     // [256]
{
    __shared__ float sW[32*257];      // transposed W tile [kk][c], padded
    __shared__ float sF[16*32];       // feature tile [r][kk]
    const int t    = threadIdx.x;
    const int row0 = blockIdx.x * 16;

    float acc[16];
#pragma unroll
    for (int r = 0; r < 16; r++) acc[r] = 0.0f;

    for (int kt = 0; kt < PD; kt += 32) {
#pragma unroll
        for (int i = 0; i < 32; i++) {
            int e  = i * 256 + t;
            int kk = e & 31;
            int c  = e >> 5;
            sW[kk*257 + c] = Wf[c*PD + kt + kk];
        }
#pragma unroll
        for (int i = 0; i < 2; i++) {
            int e = i * 256 + t;     // 512 elems
            int r = e >> 5, kk = e & 31;
            sF[r*32 + kk] = feat[(row0 + r)*PD + kt + kk];
        }
        __syncthreads();
#pragma unroll
        for (int kk = 0; kk < 32; kk++) {
            float w = sW[kk*257 + t];
#pragma unroll
            for (int r = 0; r < 16; r++)
                acc[r] = fmaf(sF[r*32 + kk], w, acc[r]);
        }
        __syncthreads();
    }
    float b = bf[t];
#pragma unroll
    for (int r = 0; r < 16; r++)
        g_pf[(size_t)(row0 + r)*GD + t] = acc[r] + b;
}

// ======================================================================
// Fused binning: count -> scan -> scatter, ONE block, smem counters.
// ======================================================================
__global__ __launch_bounds__(1024) void bin_all_kernel(const float* __restrict__ pc)
{
    __shared__ int scnt[NCELLS];   // 16 KB
    __shared__ int wsum[32];
    const int t = threadIdx.x;
    const float2* __restrict__ pc2 = (const float2*)pc;

    for (int i = t; i < NCELLS; i += 1024) scnt[i] = 0;
    __syncthreads();

    for (int n = t; n < NPTS; n += 1024) {
        float2 p = pc2[n];
        atomicAdd(&scnt[cell_of(p.x, p.y)], 1);
    }
    __syncthreads();

    int v[4], s = 0;
#pragma unroll
    for (int i = 0; i < 4; i++) { v[i] = scnt[t*4 + i]; s += v[i]; }
    const int lane = t & 31, wid = t >> 5;
    int incl = s;
#pragma unroll
    for (int o = 1; o < 32; o <<= 1) {
        int u = __shfl_up_sync(0xffffffffu, incl, o);
        if (lane >= o) incl += u;
    }
    if (lane == 31) wsum[wid] = incl;
    __syncthreads();
    if (wid == 0) {
        int ws = wsum[lane];
#pragma unroll
        for (int o = 1; o < 32; o <<= 1) {
            int u = __shfl_up_sync(0xffffffffu, ws, o);
            if (lane >= o) ws += u;
        }
        wsum[lane] = ws;
    }
    __syncthreads();
    int run = (wid > 0 ? wsum[wid-1] : 0) + incl - s;
    int starts[4];
#pragma unroll
    for (int i = 0; i < 4; i++) {
        starts[i] = run;
        g_start[t*4 + i] = run;
        run += v[i];
    }
    if (t == 1023) g_start[NCELLS] = run;
    __syncthreads();
#pragma unroll
    for (int i = 0; i < 4; i++) scnt[t*4 + i] = starts[i];
    __syncthreads();

    for (int n = t; n < NPTS; n += 1024) {
        float2 p = pc2[n];
        int pos = atomicAdd(&scnt[cell_of(p.x, p.y)], 1);
        g_pts[pos] = make_float4(p.x, p.y, sum_sq(p.x, p.y), __int_as_float(n));
    }
}

// ======================================================================
// Kernel: exact KNN (K=32), one block (128 threads) per grid point.
// Bit-exact dist2; bitonic sort by (dist2, idx).  [R3-proven]
// ======================================================================
__global__ __launch_bounds__(128) void knn_kernel()
{
    __shared__ float s_d[CAP];
    __shared__ int   s_i[CAP];
    __shared__ int   s_cnt;

    const int g   = blockIdx.x;
    const int tid = threadIdx.x;
    const int wx = g % WW, hy = g / WW;
    const float gx = grid_coord(wx), gy = grid_coord(hy);
    const float g2 = sum_sq(gx, gy);

    float R2 = 0.0015f;
    int cnt = 0;
    for (int iter = 0; iter < 24; iter++) {
        if (tid == 0) s_cnt = 0;
        __syncthreads();
        float R = sqrtf(R2);
        int cx0 = max(0,    (int)floorf((gx - R) * NC));
        int cx1 = min(NC-1, (int)floorf((gx + R) * NC));
        int cy0 = max(0,    (int)floorf((gy - R) * NC));
        int cy1 = min(NC-1, (int)floorf((gy + R) * NC));
        for (int cy = cy0; cy <= cy1; cy++) {
            int b = g_start[cy*NC + cx0];
            int e = g_start[cy*NC + cx1 + 1];
            for (int j = b + tid; j < e; j += 128) {
                float4 p = g_pts[j];
                float m = dot_ref(gx, gy, p.x, p.y);
                float d = dist2_ref(g2, m, p.z);
                if (d <= R2) {
                    int pos = atomicAdd(&s_cnt, 1);
                    if (pos < CAP) { s_d[pos] = d; s_i[pos] = __float_as_int(p.w); }
                }
            }
        }
        __syncthreads();
        cnt = s_cnt;
        if (cnt >= KNN && cnt <= CAP) break;
        R2 = (cnt < KNN) ? R2 * 2.0f : R2 * 0.5f;
        __syncthreads();
    }

    int M = KNN;
    while (M < cnt) M <<= 1;
    for (int j = cnt + tid; j < M; j += 128) { s_d[j] = FLT_MAX; s_i[j] = 0x7fffffff; }
    __syncthreads();

    for (int len = 2; len <= M; len <<= 1) {
        for (int stride = len >> 1; stride > 0; stride >>= 1) {
            for (int j = tid; j < (M >> 1); j += 128) {
                int i  = 2*j - (j & (stride - 1));
                int ip = i + stride;
                float d1 = s_d[i], d2 = s_d[ip];
                int   i1 = s_i[i], i2 = s_i[ip];
                bool up = ((i & len) == 0);
                bool gt = (d1 > d2) || (d1 == d2 && i1 > i2);
                bool lt = (d1 < d2) || (d1 == d2 && i1 < i2);
                if (up ? gt : lt) {
                    s_d[i] = d2; s_d[ip] = d1;
                    s_i[i] = i2; s_i[ip] = i1;
                }
            }
            __syncthreads();
        }
    }
    if (tid < KNN) g_knn[g*KNN + tid] = s_i[tid];
}

// ======================================================================
// Kernel: attention MLP + softmax + weighted gather.
// WARP PER GRID POINT (K=32 == warp width). 8 warps/block.
//   lane = neighbor: MLP + logit; softmax via warp shuffles.
//   gather: 32 iterations, 2 coalesced LDG.128 per iteration cover the
//   full 1KB feature row; lane owns cols [4l..4l+3] and [128+4l..131+4l].
// ======================================================================
__global__ __launch_bounds__(256) void attn_gather_kernel(
    const float* __restrict__ pc,
    const float* __restrict__ W1, const float* __restrict__ b1,
    const float* __restrict__ W2, const float* __restrict__ b2)
{
    __shared__ __align__(16) float4 sW14[HID];   // (w0,w1,w2,b1)
    __shared__ float  sW2[HID];
    __shared__ float  swt[GPB][KNN];
    __shared__ int    soff[GPB][KNN];            // float4 row offsets

    const int t = threadIdx.x;
    const int w = t >> 5;          // local grid point
    const int l = t & 31;          // lane = neighbor index
    const int g = blockIdx.x * GPB + w;

    if (t < HID) {
        sW14[t] = make_float4(W1[t*3], W1[t*3+1], W1[t*3+2], b1[t]);
        sW2[t]  = W2[t];
    }

    const int wx = g % WW, hy = g / WW;
    const float gx = grid_coord(wx), gy = grid_coord(hy);

    const int id = g_knn[g*KNN + l];
    const float px = pc[2*id], py = pc[2*id+1];
    const float dx = __fsub_rn(gx, px), dy = __fsub_rn(gy, py);
    const float dd = sqrtf(sum_sq(dx, dy));
    __syncthreads();   // sW14/sW2 ready

    // MLP: this lane evaluates all 64 hidden units for its neighbor
    float acc = 0.0f;
#pragma unroll 16
    for (int j = 0; j < HID; j++) {
        float4 wv = sW14[j];
        float pre = fmaf(wv.x, dx, fmaf(wv.y, dy, fmaf(wv.z, dd, wv.w)));
        float ge  = 0.5f * pre * (1.0f + erff(pre * 0.70710678118654752f));
        acc = fmaf(sW2[j], ge, acc);
    }
    float logit = acc + b2[0];

    // warp softmax over the 32 neighbors
    float m = logit;
#pragma unroll
    for (int o = 16; o >= 1; o >>= 1) m = fmaxf(m, __shfl_xor_sync(0xffffffffu, m, o));
    float e = expf(logit - m);
    float s = e;
#pragma unroll
    for (int o = 16; o >= 1; o >>= 1) s += __shfl_xor_sync(0xffffffffu, s, o);
    swt[w][l]  = e / s;
    soff[w][l] = id * (GD/4);
    __syncwarp();

    // weighted gather: full row per iteration, 2 coalesced LDG.128
    const float4* __restrict__ pf4 = (const float4*)g_pf;
    float4 a0 = make_float4(0.f,0.f,0.f,0.f);
    float4 a1 = make_float4(0.f,0.f,0.f,0.f);
#pragma unroll 8
    for (int k = 0; k < KNN; k++) {
        float wk = swt[w][k];
        int   ro = soff[w][k];
        float4 v0 = pf4[(size_t)ro + l];
        float4 v1 = pf4[(size_t)ro + 32 + l];
        a0.x = fmaf(wk, v0.x, a0.x); a0.y = fmaf(wk, v0.y, a0.y);
        a0.z = fmaf(wk, v0.z, a0.z); a0.w = fmaf(wk, v0.w, a0.w);
        a1.x = fmaf(wk, v1.x, a1.x); a1.y = fmaf(wk, v1.y, a1.y);
        a1.z = fmaf(wk, v1.z, a1.z); a1.w = fmaf(wk, v1.w, a1.w);
    }
    float4* mid4 = (float4*)g_mid;
    mid4[(size_t)g*(GD/4) + l]      = a0;
    mid4[(size_t)g*(GD/4) + 32 + l] = a1;
}

// ======================================================================
// Kernel: out = mid @ W_out^T + b_out, then LayerNorm. 32 rows/block.
// R3-proven version. Dynamic smem: Wt[64][257] + In[32][64] + Out[32][257]
// ======================================================================
__global__ __launch_bounds__(256) void outproj_ln_kernel(
    const float* __restrict__ Wo,   // [256,256]
    const float* __restrict__ bo,
    const float* __restrict__ lng,
    const float* __restrict__ lnb,
    float* __restrict__ out)
{
    extern __shared__ float sm[];
    float* sW  = sm;                    // 64*257
    float* sIn = sm + 64*257;           // 32*64
    float* sOut= sIn + 32*64;           // 32*257
    __shared__ float sMu[32], sRs[32];

    const int t    = threadIdx.x;
    const int row0 = blockIdx.x * 32;

    float acc[32];
#pragma unroll
    for (int r = 0; r < 32; r++) acc[r] = 0.0f;

    for (int kt = 0; kt < GD; kt += 64) {
#pragma unroll
        for (int i = 0; i < 64; i++) {
            int e  = i * 256 + t;
            int kk = e & 63;
            int c  = e >> 6;
            sW[kk*257 + c] = Wo[c*GD + kt + kk];
        }
#pragma unroll
        for (int i = 0; i < 8; i++) {
            int e = i * 256 + t;   // 2048 elems
            int r = e >> 6, kk = e & 63;
            sIn[r*64 + kk] = g_mid[(size_t)(row0 + r)*GD + kt + kk];
        }
        __syncthreads();
#pragma unroll
        for (int kk = 0; kk < 64; kk++) {
            float w = sW[kk*257 + t];
#pragma unroll
            for (int r = 0; r < 32; r++)
                acc[r] = fmaf(sIn[r*64 + kk], w, acc[r]);
        }
        __syncthreads();
    }

    float bb = bo[t];
#pragma unroll
    for (int r = 0; r < 32; r++) sOut[r*257 + t] = acc[r] + bb;
    __syncthreads();

    const int lane = t & 31, wid = t >> 5;
    for (int r = wid; r < 32; r += 8) {
        float s = 0.0f;
#pragma unroll
        for (int i = lane; i < GD; i += 32) s += sOut[r*257 + i];
#pragma unroll
        for (int o = 16; o >= 1; o >>= 1) s += __shfl_xor_sync(0xffffffffu, s, o);
        float mu = s * (1.0f / GD);
        float v = 0.0f;
#pragma unroll
        for (int i = lane; i < GD; i += 32) {
            float d = sOut[r*257 + i] - mu;
            v = fmaf(d, d, v);
        }
#pragma unroll
        for (int o = 16; o >= 1; o >>= 1) v += __shfl_xor_sync(0xffffffffu, v, o);
        if (lane == 0) { sMu[r] = mu; sRs[r] = rsqrtf(v * (1.0f / GD) + EPSLN); }
    }
    __syncthreads();

    float gsc = lng[t], bsc = lnb[t];
#pragma unroll
    for (int r = 0; r < 32; r++) {
        float val = (sOut[r*257 + t] - sMu[r]) * sRs[r] * gsc + bsc;
        out[(size_t)(row0 + r)*GD + t] = val;
    }
}

// ======================================================================
// launcher
// ======================================================================
extern "C" void kernel_launch(void* const* d_in, const int* in_sizes, int n_in,
                              void* d_out, int out_size)
{
    const float* point_features = (const float*)d_in[0];
    const float* point_coords   = (const float*)d_in[1];
    const float* W_feat         = (const float*)d_in[2];
    const float* b_feat         = (const float*)d_in[3];
    const float* W1             = (const float*)d_in[4];
    const float* b1             = (const float*)d_in[5];
    const float* W2             = (const float*)d_in[6];
    const float* b2             = (const float*)d_in[7];
    const float* W_out          = (const float*)d_in[8];
    const float* b_out          = (const float*)d_in[9];
    const float* ln_g           = (const float*)d_in[10];
    const float* ln_b           = (const float*)d_in[11];
    float* out = (float*)d_out;

    const int SMEM8 = (64*257 + 32*64 + 32*257) * (int)sizeof(float);
    cudaFuncSetAttribute(outproj_ln_kernel,
                         cudaFuncAttributeMaxDynamicSharedMemorySize, SMEM8);

    // 1. fused binning
    bin_all_kernel<<<1, 1024>>>(point_coords);

    // 2. feature projection (R3-proven)
    pf_kernel<<<NPTS/16, 256>>>(point_features, W_feat, b_feat);

    // 3. exact KNN (R3-proven)
    knn_kernel<<<G, 128>>>();

    // 4. attention + gather (warp per grid point)
    attn_gather_kernel<<<G/GPB, 256>>>(point_coords, W1, b1, W2, b2);

    // 5. output projection + layernorm (R3-proven)
    outproj_ln_kernel<<<G/32, 256, SMEM8>>>(W_out, b_out, ln_g, ln_b, out);
}

// round 8
// speedup vs baseline: 1.4475x; 1.1879x over previous
#include <cuda_runtime.h>
#include <cuda_bf16.h>
#include <math.h>
#include <float.h>

// ---------------- problem constants (fixed dataset) ----------------
#define NPTS    20000
#define PD      64          // point feature dim
#define GD      256         // grid feature dim
#define HH      96
#define WW      96
#define G       (HH*WW)     // 9216 grid points
#define KNN     32
#define HID     64
#define NC      64          // bin grid 64x64
#define NCELLS  (NC*NC)
#define CAP     1024        // candidate capacity per grid point
#define EPSLN   1e-5f
#define GPB     8           // grid points per attn block (8 warps)

// step = f32(1/95), exactly as JAX f32 linspace computes it
#define STEP    (1.0f/95.0f)

// ---------------- scratch (device globals, no allocations) ----------------
__device__ float  g_pf[NPTS*GD];       // projected point features (20.5 MB)
__device__ int    g_start[NCELLS+1];
__device__ float4 g_pts[NPTS];         // (px, py, p2, idx-as-float), binned order
__device__ int    g_knn[G*KNN];
__device__ float  g_mid[G*GD];         // aggregated features before out-proj

// exact-rounding helpers for the KNN distance path (must bit-match reference)
__device__ __forceinline__ float grid_coord(int i) {
    return __fmul_rn((float)i, STEP);
}
__device__ __forceinline__ float sum_sq(float x, float y) {
    return __fadd_rn(__fmul_rn(x, x), __fmul_rn(y, y));
}
__device__ __forceinline__ float dot_ref(float gx, float gy, float px, float py) {
    return __fadd_rn(__fmul_rn(gx, px), __fmul_rn(gy, py));
}
__device__ __forceinline__ float dist2_ref(float g2, float m, float p2) {
    return __fadd_rn(__fsub_rn(g2, __fmul_rn(2.0f, m)), p2);
}
__device__ __forceinline__ int cell_of(float px, float py) {
    int cx = (int)(px * NC); cx = min(max(cx, 0), NC-1);
    int cy = (int)(py * NC); cy = min(max(cy, 0), NC-1);
    return cy * NC + cx;
}

// ======================================================================
// Kernel 1: pf = feat @ W_feat^T + b_feat   [20000 x 256]   [R5-proven]
// 32 rows x 256 cols per block; thread tile 8r x 4c; LDS.128 inner loop.
// ======================================================================
__global__ __launch_bounds__(256) void pf_kernel(
    const float* __restrict__ feat,   // [NPTS,64]
    const float* __restrict__ Wf,     // [256,64]
    const float* __restrict__ bf)     // [256]
{
    __shared__ __align__(16) float sW[32*260];   // [kk][c]
    __shared__ __align__(16) float sF[32*36];    // [kk][r]
    const int t    = threadIdx.x;
    const int row0 = blockIdx.x * 32;
    const int ty   = t >> 6;           // 0..3 -> r0 = ty*8
    const int tx   = t & 63;           // c0 = tx*4
    const int r0   = ty * 8;
    const int c0   = tx * 4;

    const float4* feat4 = (const float4*)feat;   // row stride 16
    const float4* Wf4   = (const float4*)Wf;     // row stride 16

    float4 acc[8];
#pragma unroll
    for (int r = 0; r < 8; r++) acc[r] = make_float4(0.f,0.f,0.f,0.f);

    for (int kt = 0; kt < PD; kt += 32) {
#pragma unroll
        for (int i = 0; i < 8; i++) {
            int lin = i * 256 + t;          // 0..2047
            int kk4 = lin & 7;              // kk = kk4*4
            int c   = lin >> 3;             // 0..255
            float4 v = Wf4[c*16 + (kt>>2) + kk4];
            sW[(kk4*4+0)*260 + c] = v.x;
            sW[(kk4*4+1)*260 + c] = v.y;
            sW[(kk4*4+2)*260 + c] = v.z;
            sW[(kk4*4+3)*260 + c] = v.w;
        }
        {
            int kk4 = t & 7;
            int r   = t >> 3;               // 0..31
            float4 v = feat4[(size_t)(row0 + r)*16 + (kt>>2) + kk4];
            sF[(kk4*4+0)*36 + r] = v.x;
            sF[(kk4*4+1)*36 + r] = v.y;
            sF[(kk4*4+2)*36 + r] = v.z;
            sF[(kk4*4+3)*36 + r] = v.w;
        }
        __syncthreads();
#pragma unroll
        for (int kk = 0; kk < 32; kk++) {
            float4 w  = *(const float4*)&sW[kk*260 + c0];
            float4 fA = *(const float4*)&sF[kk*36 + r0];
            float4 fB = *(const float4*)&sF[kk*36 + r0 + 4];
            acc[0].x = fmaf(fA.x, w.x, acc[0].x); acc[0].y = fmaf(fA.x, w.y, acc[0].y);
            acc[0].z = fmaf(fA.x, w.z, acc[0].z); acc[0].w = fmaf(fA.x, w.w, acc[0].w);
            acc[1].x = fmaf(fA.y, w.x, acc[1].x); acc[1].y = fmaf(fA.y, w.y, acc[1].y);
            acc[1].z = fmaf(fA.y, w.z, acc[1].z); acc[1].w = fmaf(fA.y, w.w, acc[1].w);
            acc[2].x = fmaf(fA.z, w.x, acc[2].x); acc[2].y = fmaf(fA.z, w.y, acc[2].y);
            acc[2].z = fmaf(fA.z, w.z, acc[2].z); acc[2].w = fmaf(fA.z, w.w, acc[2].w);
            acc[3].x = fmaf(fA.w, w.x, acc[3].x); acc[3].y = fmaf(fA.w, w.y, acc[3].y);
            acc[3].z = fmaf(fA.w, w.z, acc[3].z); acc[3].w = fmaf(fA.w, w.w, acc[3].w);
            acc[4].x = fmaf(fB.x, w.x, acc[4].x); acc[4].y = fmaf(fB.x, w.y, acc[4].y);
            acc[4].z = fmaf(fB.x, w.z, acc[4].z); acc[4].w = fmaf(fB.x, w.w, acc[4].w);
            acc[5].x = fmaf(fB.y, w.x, acc[5].x); acc[5].y = fmaf(fB.y, w.y, acc[5].y);
            acc[5].z = fmaf(fB.y, w.z, acc[5].z); acc[5].w = fmaf(fB.y, w.w, acc[5].w);
            acc[6].x = fmaf(fB.z, w.x, acc[6].x); acc[6].y = fmaf(fB.z, w.y, acc[6].y);
            acc[6].z = fmaf(fB.z, w.z, acc[6].z); acc[6].w = fmaf(fB.z, w.w, acc[6].w);
            acc[7].x = fmaf(fB.w, w.x, acc[7].x); acc[7].y = fmaf(fB.w, w.y, acc[7].y);
            acc[7].z = fmaf(fB.w, w.z, acc[7].z); acc[7].w = fmaf(fB.w, w.w, acc[7].w);
        }
        __syncthreads();
    }
    float4 b4 = *(const float4*)&bf[c0];
    float4* out4 = (float4*)g_pf;
#pragma unroll
    for (int r = 0; r < 8; r++) {
        float4 v = acc[r];
        v.x += b4.x; v.y += b4.y; v.z += b4.z; v.w += b4.w;
        out4[(size_t)(row0 + r0 + r)*64 + tx] = v;
    }
}

// ======================================================================
// Fused binning: count -> scan -> scatter, ONE block, smem counters.
// ======================================================================
__global__ __launch_bounds__(1024) void bin_all_kernel(const float* __restrict__ pc)
{
    __shared__ int scnt[NCELLS];   // 16 KB
    __shared__ int wsum[32];
    const int t = threadIdx.x;
    const float2* __restrict__ pc2 = (const float2*)pc;

    for (int i = t; i < NCELLS; i += 1024) scnt[i] = 0;
    __syncthreads();

    for (int n = t; n < NPTS; n += 1024) {
        float2 p = pc2[n];
        atomicAdd(&scnt[cell_of(p.x, p.y)], 1);
    }
    __syncthreads();

    int v[4], s = 0;
#pragma unroll
    for (int i = 0; i < 4; i++) { v[i] = scnt[t*4 + i]; s += v[i]; }
    const int lane = t & 31, wid = t >> 5;
    int incl = s;
#pragma unroll
    for (int o = 1; o < 32; o <<= 1) {
        int u = __shfl_up_sync(0xffffffffu, incl, o);
        if (lane >= o) incl += u;
    }
    if (lane == 31) wsum[wid] = incl;
    __syncthreads();
    if (wid == 0) {
        int ws = wsum[lane];
#pragma unroll
        for (int o = 1; o < 32; o <<= 1) {
            int u = __shfl_up_sync(0xffffffffu, ws, o);
            if (lane >= o) ws += u;
        }
        wsum[lane] = ws;
    }
    __syncthreads();
    int run = (wid > 0 ? wsum[wid-1] : 0) + incl - s;
    int starts[4];
#pragma unroll
    for (int i = 0; i < 4; i++) {
        starts[i] = run;
        g_start[t*4 + i] = run;
        run += v[i];
    }
    if (t == 1023) g_start[NCELLS] = run;
    __syncthreads();
#pragma unroll
    for (int i = 0; i < 4; i++) scnt[t*4 + i] = starts[i];
    __syncthreads();

    for (int n = t; n < NPTS; n += 1024) {
        float2 p = pc2[n];
        int pos = atomicAdd(&scnt[cell_of(p.x, p.y)], 1);
        g_pts[pos] = make_float4(p.x, p.y, sum_sq(p.x, p.y), __int_as_float(n));
    }
}

// ======================================================================
// Kernel: exact KNN (K=32), one block (128 threads) per grid point.
// Bit-exact dist2; bitonic sort by (dist2, idx).  [R3-proven]
// ======================================================================
__global__ __launch_bounds__(128) void knn_kernel()
{
    __shared__ float s_d[CAP];
    __shared__ int   s_i[CAP];
    __shared__ int   s_cnt;

    const int g   = blockIdx.x;
    const int tid = threadIdx.x;
    const int wx = g % WW, hy = g / WW;
    const float gx = grid_coord(wx), gy = grid_coord(hy);
    const float g2 = sum_sq(gx, gy);

    float R2 = 0.0015f;
    int cnt = 0;
    for (int iter = 0; iter < 24; iter++) {
        if (tid == 0) s_cnt = 0;
        __syncthreads();
        float R = sqrtf(R2);
        int cx0 = max(0,    (int)floorf((gx - R) * NC));
        int cx1 = min(NC-1, (int)floorf((gx + R) * NC));
        int cy0 = max(0,    (int)floorf((gy - R) * NC));
        int cy1 = min(NC-1, (int)floorf((gy + R) * NC));
        for (int cy = cy0; cy <= cy1; cy++) {
            int b = g_start[cy*NC + cx0];
            int e = g_start[cy*NC + cx1 + 1];
            for (int j = b + tid; j < e; j += 128) {
                float4 p = g_pts[j];
                float m = dot_ref(gx, gy, p.x, p.y);
                float d = dist2_ref(g2, m, p.z);
                if (d <= R2) {
                    int pos = atomicAdd(&s_cnt, 1);
                    if (pos < CAP) { s_d[pos] = d; s_i[pos] = __float_as_int(p.w); }
                }
            }
        }
        __syncthreads();
        cnt = s_cnt;
        if (cnt >= KNN && cnt <= CAP) break;
        R2 = (cnt < KNN) ? R2 * 2.0f : R2 * 0.5f;
        __syncthreads();
    }

    int M = KNN;
    while (M < cnt) M <<= 1;
    for (int j = cnt + tid; j < M; j += 128) { s_d[j] = FLT_MAX; s_i[j] = 0x7fffffff; }
    __syncthreads();

    for (int len = 2; len <= M; len <<= 1) {
        for (int stride = len >> 1; stride > 0; stride >>= 1) {
            for (int j = tid; j < (M >> 1); j += 128) {
                int i  = 2*j - (j & (stride - 1));
                int ip = i + stride;
                float d1 = s_d[i], d2 = s_d[ip];
                int   i1 = s_i[i], i2 = s_i[ip];
                bool up = ((i & len) == 0);
                bool gt = (d1 > d2) || (d1 == d2 && i1 > i2);
                bool lt = (d1 < d2) || (d1 == d2 && i1 < i2);
                if (up ? gt : lt) {
                    s_d[i] = d2; s_d[ip] = d1;
                    s_i[i] = i2; s_i[ip] = i1;
                }
            }
            __syncthreads();
        }
    }
    if (tid < KNN) g_knn[g*KNN + tid] = s_i[tid];
}

// ======================================================================
// Kernel: attention MLP + softmax + weighted gather.  [R7-proven]
// WARP PER GRID POINT (K=32 == warp width). 8 warps/block.
// ======================================================================
__global__ __launch_bounds__(256) void attn_gather_kernel(
    const float* __restrict__ pc,
    const float* __restrict__ W1, const float* __restrict__ b1,
    const float* __restrict__ W2, const float* __restrict__ b2)
{
    __shared__ __align__(16) float4 sW14[HID];   // (w0,w1,w2,b1)
    __shared__ float  sW2[HID];
    __shared__ float  swt[GPB][KNN];
    __shared__ int    soff[GPB][KNN];            // float4 row offsets

    const int t = threadIdx.x;
    const int w = t >> 5;          // local grid point
    const int l = t & 31;          // lane = neighbor index
    const int g = blockIdx.x * GPB + w;

    if (t < HID) {
        sW14[t] = make_float4(W1[t*3], W1[t*3+1], W1[t*3+2], b1[t]);
        sW2[t]  = W2[t];
    }

    const int wx = g % WW, hy = g / WW;
    const float gx = grid_coord(wx), gy = grid_coord(hy);

    const int id = g_knn[g*KNN + l];
    const float px = pc[2*id], py = pc[2*id+1];
    const float dx = __fsub_rn(gx, px), dy = __fsub_rn(gy, py);
    const float dd = sqrtf(sum_sq(dx, dy));
    __syncthreads();   // sW14/sW2 ready

    // MLP: this lane evaluates all 64 hidden units for its neighbor
    float acc = 0.0f;
#pragma unroll 16
    for (int j = 0; j < HID; j++) {
        float4 wv = sW14[j];
        float pre = fmaf(wv.x, dx, fmaf(wv.y, dy, fmaf(wv.z, dd, wv.w)));
        float ge  = 0.5f * pre * (1.0f + erff(pre * 0.70710678118654752f));
        acc = fmaf(sW2[j], ge, acc);
    }
    float logit = acc + b2[0];

    // warp softmax over the 32 neighbors
    float m = logit;
#pragma unroll
    for (int o = 16; o >= 1; o >>= 1) m = fmaxf(m, __shfl_xor_sync(0xffffffffu, m, o));
    float e = expf(logit - m);
    float s = e;
#pragma unroll
    for (int o = 16; o >= 1; o >>= 1) s += __shfl_xor_sync(0xffffffffu, s, o);
    swt[w][l]  = e / s;
    soff[w][l] = id * (GD/4);
    __syncwarp();

    // weighted gather: full row per iteration, 2 coalesced LDG.128
    const float4* __restrict__ pf4 = (const float4*)g_pf;
    float4 a0 = make_float4(0.f,0.f,0.f,0.f);
    float4 a1 = make_float4(0.f,0.f,0.f,0.f);
#pragma unroll 8
    for (int k = 0; k < KNN; k++) {
        float wk = swt[w][k];
        int   ro = soff[w][k];
        float4 v0 = pf4[(size_t)ro + l];
        float4 v1 = pf4[(size_t)ro + 32 + l];
        a0.x = fmaf(wk, v0.x, a0.x); a0.y = fmaf(wk, v0.y, a0.y);
        a0.z = fmaf(wk, v0.z, a0.z); a0.w = fmaf(wk, v0.w, a0.w);
        a1.x = fmaf(wk, v1.x, a1.x); a1.y = fmaf(wk, v1.y, a1.y);
        a1.z = fmaf(wk, v1.z, a1.z); a1.w = fmaf(wk, v1.w, a1.w);
    }
    float4* mid4 = (float4*)g_mid;
    mid4[(size_t)g*(GD/4) + l]      = a0;
    mid4[(size_t)g*(GD/4) + 32 + l] = a1;
}

// ======================================================================
// Kernel: out = mid @ W_out^T + b_out, then LayerNorm.   [R5-proven]
// 32 rows x 256 cols per block; thread tile 8r x 4c; LDS.128 inner loop.
// ======================================================================
__global__ __launch_bounds__(256) void outproj_ln_kernel(
    const float* __restrict__ Wo,   // [256,256]
    const float* __restrict__ bo,
    const float* __restrict__ lng,
    const float* __restrict__ lnb,
    float* __restrict__ out)
{
    __shared__ __align__(16) float sW[32*260];   // [kk][c]; reused as sOut [r][c]
    __shared__ __align__(16) float sF[32*36];    // [kk][r]
    __shared__ float sMu[32], sRs[32];

    const int t    = threadIdx.x;
    const int row0 = blockIdx.x * 32;
    const int ty   = t >> 6;
    const int tx   = t & 63;
    const int r0   = ty * 8;
    const int c0   = tx * 4;

    const float4* Wo4  = (const float4*)Wo;    // row stride 64
    const float4* mid4 = (const float4*)g_mid; // row stride 64

    float4 acc[8];
#pragma unroll
    for (int r = 0; r < 8; r++) acc[r] = make_float4(0.f,0.f,0.f,0.f);

    for (int kt = 0; kt < GD; kt += 32) {
#pragma unroll
        for (int i = 0; i < 8; i++) {
            int lin = i * 256 + t;
            int kk4 = lin & 7;
            int c   = lin >> 3;
            float4 v = Wo4[c*64 + (kt>>2) + kk4];
            sW[(kk4*4+0)*260 + c] = v.x;
            sW[(kk4*4+1)*260 + c] = v.y;
            sW[(kk4*4+2)*260 + c] = v.z;
            sW[(kk4*4+3)*260 + c] = v.w;
        }
        {
            int kk4 = t & 7;
            int r   = t >> 3;
            float4 v = mid4[(size_t)(row0 + r)*64 + (kt>>2) + kk4];
            sF[(kk4*4+0)*36 + r] = v.x;
            sF[(kk4*4+1)*36 + r] = v.y;
            sF[(kk4*4+2)*36 + r] = v.z;
            sF[(kk4*4+3)*36 + r] = v.w;
        }
        __syncthreads();
#pragma unroll
        for (int kk = 0; kk < 32; kk++) {
            float4 w  = *(const float4*)&sW[kk*260 + c0];
            float4 fA = *(const float4*)&sF[kk*36 + r0];
            float4 fB = *(const float4*)&sF[kk*36 + r0 + 4];
            acc[0].x = fmaf(fA.x, w.x, acc[0].x); acc[0].y = fmaf(fA.x, w.y, acc[0].y);
            acc[0].z = fmaf(fA.x, w.z, acc[0].z); acc[0].w = fmaf(fA.x, w.w, acc[0].w);
            acc[1].x = fmaf(fA.y, w.x, acc[1].x); acc[1].y = fmaf(fA.y, w.y, acc[1].y);
            acc[1].z = fmaf(fA.y, w.z, acc[1].z); acc[1].w = fmaf(fA.y, w.w, acc[1].w);
            acc[2].x = fmaf(fA.z, w.x, acc[2].x); acc[2].y = fmaf(fA.z, w.y, acc[2].y);
            acc[2].z = fmaf(fA.z, w.z, acc[2].z); acc[2].w = fmaf(fA.z, w.w, acc[2].w);
            acc[3].x = fmaf(fA.w, w.x, acc[3].x); acc[3].y = fmaf(fA.w, w.y, acc[3].y);
            acc[3].z = fmaf(fA.w, w.z, acc[3].z); acc[3].w = fmaf(fA.w, w.w, acc[3].w);
            acc[4].x = fmaf(fB.x, w.x, acc[4].x); acc[4].y = fmaf(fB.x, w.y, acc[4].y);
            acc[4].z = fmaf(fB.x, w.z, acc[4].z); acc[4].w = fmaf(fB.x, w.w, acc[4].w);
            acc[5].x = fmaf(fB.y, w.x, acc[5].x); acc[5].y = fmaf(fB.y, w.y, acc[5].y);
            acc[5].z = fmaf(fB.y, w.z, acc[5].z); acc[5].w = fmaf(fB.y, w.w, acc[5].w);
            acc[6].x = fmaf(fB.z, w.x, acc[6].x); acc[6].y = fmaf(fB.z, w.y, acc[6].y);
            acc[6].z = fmaf(fB.z, w.z, acc[6].z); acc[6].w = fmaf(fB.z, w.w, acc[6].w);
            acc[7].x = fmaf(fB.w, w.x, acc[7].x); acc[7].y = fmaf(fB.w, w.y, acc[7].y);
            acc[7].z = fmaf(fB.w, w.z, acc[7].z); acc[7].w = fmaf(fB.w, w.w, acc[7].w);
        }
        __syncthreads();
    }

    float4 b4 = *(const float4*)&bo[c0];
#pragma unroll
    for (int r = 0; r < 8; r++) {
        float4 v = acc[r];
        v.x += b4.x; v.y += b4.y; v.z += b4.z; v.w += b4.w;
        *(float4*)&sW[(r0 + r)*260 + c0] = v;
    }
    __syncthreads();

    const int lane = t & 31, wid = t >> 5;
    for (int r = wid; r < 32; r += 8) {
        float s = 0.0f;
#pragma unroll
        for (int i = lane; i < GD; i += 32) s += sW[r*260 + i];
#pragma unroll
        for (int o = 16; o >= 1; o >>= 1) s += __shfl_xor_sync(0xffffffffu, s, o);
        float mu = s * (1.0f / GD);
        float v = 0.0f;
#pragma unroll
        for (int i = lane; i < GD; i += 32) {
            float d = sW[r*260 + i] - mu;
            v = fmaf(d, d, v);
        }
#pragma unroll
        for (int o = 16; o >= 1; o >>= 1) v += __shfl_xor_sync(0xffffffffu, v, o);
        if (lane == 0) { sMu[r] = mu; sRs[r] = rsqrtf(v * (1.0f / GD) + EPSLN); }
    }
    __syncthreads();

    float4 g4 = *(const float4*)&lng[c0];
    float4 be4 = *(const float4*)&lnb[c0];
    float4* out4 = (float4*)out;
#pragma unroll
    for (int r = 0; r < 8; r++) {
        int rr = r0 + r;
        float mu = sMu[rr], rs = sRs[rr];
        float4 v = *(const float4*)&sW[rr*260 + c0];
        v.x = (v.x - mu) * rs * g4.x + be4.x;
        v.y = (v.y - mu) * rs * g4.y + be4.y;
        v.z = (v.z - mu) * rs * g4.z + be4.z;
        v.w = (v.w - mu) * rs * g4.w + be4.w;
        out4[(size_t)(row0 + rr)*64 + tx] = v;
    }
}

// ======================================================================
// launcher
// ======================================================================
extern "C" void kernel_launch(void* const* d_in, const int* in_sizes, int n_in,
                              void* d_out, int out_size)
{
    const float* point_features = (const float*)d_in[0];
    const float* point_coords   = (const float*)d_in[1];
    const float* W_feat         = (const float*)d_in[2];
    const float* b_feat         = (const float*)d_in[3];
    const float* W1             = (const float*)d_in[4];
    const float* b1             = (const float*)d_in[5];
    const float* W2             = (const float*)d_in[6];
    const float* b2             = (const float*)d_in[7];
    const float* W_out          = (const float*)d_in[8];
    const float* b_out          = (const float*)d_in[9];
    const float* ln_g           = (const float*)d_in[10];
    const float* ln_b           = (const float*)d_in[11];
    float* out = (float*)d_out;

    // 1. fused binning
    bin_all_kernel<<<1, 1024>>>(point_coords);

    // 2. feature projection (R5 reg-tiled)
    pf_kernel<<<NPTS/32, 256>>>(point_features, W_feat, b_feat);

    // 3. exact KNN (R3-proven)
    knn_kernel<<<G, 128>>>();

    // 4. attention + gather (R7 warp per grid point)
    attn_gather_kernel<<<G/GPB, 256>>>(point_coords, W1, b1, W2, b2);

    // 5. output projection + layernorm (R5 reg-tiled)
    outproj_ln_kernel<<<G/32, 256>>>(W_out, b_out, ln_g, ln_b, out);
}

// round 9
// speedup vs baseline: 1.6309x; 1.1267x over previous
#include <cuda_runtime.h>
#include <cuda_bf16.h>
#include <math.h>
#include <float.h>

// ---------------- problem constants (fixed dataset) ----------------
#define NPTS    20000
#define PD      64          // point feature dim
#define GD      256         // grid feature dim
#define HH      96
#define WW      96
#define G       (HH*WW)     // 9216 grid points
#define KNN     32
#define HID     64
#define NC      64          // bin grid 64x64
#define NCELLS  (NC*NC)
#define EPSLN   1e-5f
#define GPB     8           // grid points per attn/knn block (8 warps)

// step = f32(1/95), exactly as JAX f32 linspace computes it
#define STEP    (1.0f/95.0f)

#define FULLMASK 0xffffffffu
#define SENT     0xffffffffffffffffull

// ---------------- scratch (device globals, no allocations) ----------------
__device__ float  g_pf[NPTS*GD];       // projected point features (20.5 MB)
__device__ int    g_start[NCELLS+1];
__device__ float4 g_pts[NPTS];         // (px, py, p2, idx-as-float), binned order
__device__ int    g_knn[G*KNN];
__device__ float  g_mid[G*GD];         // aggregated features before out-proj

// exact-rounding helpers for the KNN distance path (must bit-match reference)
__device__ __forceinline__ float grid_coord(int i) {
    return __fmul_rn((float)i, STEP);
}
__device__ __forceinline__ float sum_sq(float x, float y) {
    return __fadd_rn(__fmul_rn(x, x), __fmul_rn(y, y));
}
__device__ __forceinline__ float dot_ref(float gx, float gy, float px, float py) {
    return __fadd_rn(__fmul_rn(gx, px), __fmul_rn(gy, py));
}
__device__ __forceinline__ float dist2_ref(float g2, float m, float p2) {
    return __fadd_rn(__fsub_rn(g2, __fmul_rn(2.0f, m)), p2);
}
__device__ __forceinline__ int cell_of(float px, float py) {
    int cx = (int)(px * NC); cx = min(max(cx, 0), NC-1);
    int cy = (int)(py * NC); cy = min(max(cy, 0), NC-1);
    return cy * NC + cx;
}
// monotone float -> uint mapping (handles tiny negative fp dist2)
__device__ __forceinline__ unsigned int fkey(float d) {
    unsigned int u = __float_as_uint(d);
    return (u & 0x80000000u) ? ~u : (u | 0x80000000u);
}

// warp bitonic full sort, ascending across lanes (15 stages)
__device__ __forceinline__ unsigned long long wsort32(unsigned long long key, int lane) {
#pragma unroll
    for (int k = 2; k <= 32; k <<= 1) {
#pragma unroll
        for (int j = k >> 1; j > 0; j >>= 1) {
            unsigned long long p = __shfl_xor_sync(FULLMASK, key, j);
            bool up      = ((lane & k) == 0);
            bool keepMin = (((lane & j) == 0) == up);
            unsigned long long lo = key < p ? key : p;
            unsigned long long hi = key < p ? p : key;
            key = keepMin ? lo : hi;
        }
    }
    return key;
}
// clean a 32-length bitonic sequence into ascending order (5 stages)
__device__ __forceinline__ unsigned long long wmerge32(unsigned long long key, int lane) {
#pragma unroll
    for (int j = 16; j > 0; j >>= 1) {
        unsigned long long p = __shfl_xor_sync(FULLMASK, key, j);
        unsigned long long lo = key < p ? key : p;
        unsigned long long hi = key < p ? p : key;
        key = ((lane & j) == 0) ? lo : hi;
    }
    return key;
}

// ======================================================================
// Kernel 1: pf = feat @ W_feat^T + b_feat   [20000 x 256]   [R5/R8-proven]
// ======================================================================
__global__ __launch_bounds__(256) void pf_kernel(
    const float* __restrict__ feat,   // [NPTS,64]
    const float* __restrict__ Wf,     // [256,64]
    const float* __restrict__ bf)     // [256]
{
    __shared__ __align__(16) float sW[32*260];   // [kk][c]
    __shared__ __align__(16) float sF[32*36];    // [kk][r]
    const int t    = threadIdx.x;
    const int row0 = blockIdx.x * 32;
    const int ty   = t >> 6;
    const int tx   = t & 63;
    const int r0   = ty * 8;
    const int c0   = tx * 4;

    const float4* feat4 = (const float4*)feat;
    const float4* Wf4   = (const float4*)Wf;

    float4 acc[8];
#pragma unroll
    for (int r = 0; r < 8; r++) acc[r] = make_float4(0.f,0.f,0.f,0.f);

    for (int kt = 0; kt < PD; kt += 32) {
#pragma unroll
        for (int i = 0; i < 8; i++) {
            int lin = i * 256 + t;
            int kk4 = lin & 7;
            int c   = lin >> 3;
            float4 v = Wf4[c*16 + (kt>>2) + kk4];
            sW[(kk4*4+0)*260 + c] = v.x;
            sW[(kk4*4+1)*260 + c] = v.y;
            sW[(kk4*4+2)*260 + c] = v.z;
            sW[(kk4*4+3)*260 + c] = v.w;
        }
        {
            int kk4 = t & 7;
            int r   = t >> 3;
            float4 v = feat4[(size_t)(row0 + r)*16 + (kt>>2) + kk4];
            sF[(kk4*4+0)*36 + r] = v.x;
            sF[(kk4*4+1)*36 + r] = v.y;
            sF[(kk4*4+2)*36 + r] = v.z;
            sF[(kk4*4+3)*36 + r] = v.w;
        }
        __syncthreads();
#pragma unroll
        for (int kk = 0; kk < 32; kk++) {
            float4 w  = *(const float4*)&sW[kk*260 + c0];
            float4 fA = *(const float4*)&sF[kk*36 + r0];
            float4 fB = *(const float4*)&sF[kk*36 + r0 + 4];
            acc[0].x = fmaf(fA.x, w.x, acc[0].x); acc[0].y = fmaf(fA.x, w.y, acc[0].y);
            acc[0].z = fmaf(fA.x, w.z, acc[0].z); acc[0].w = fmaf(fA.x, w.w, acc[0].w);
            acc[1].x = fmaf(fA.y, w.x, acc[1].x); acc[1].y = fmaf(fA.y, w.y, acc[1].y);
            acc[1].z = fmaf(fA.y, w.z, acc[1].z); acc[1].w = fmaf(fA.y, w.w, acc[1].w);
            acc[2].x = fmaf(fA.z, w.x, acc[2].x); acc[2].y = fmaf(fA.z, w.y, acc[2].y);
            acc[2].z = fmaf(fA.z, w.z, acc[2].z); acc[2].w = fmaf(fA.z, w.w, acc[2].w);
            acc[3].x = fmaf(fA.w, w.x, acc[3].x); acc[3].y = fmaf(fA.w, w.y, acc[3].y);
            acc[3].z = fmaf(fA.w, w.z, acc[3].z); acc[3].w = fmaf(fA.w, w.w, acc[3].w);
            acc[4].x = fmaf(fB.x, w.x, acc[4].x); acc[4].y = fmaf(fB.x, w.y, acc[4].y);
            acc[4].z = fmaf(fB.x, w.z, acc[4].z); acc[4].w = fmaf(fB.x, w.w, acc[4].w);
            acc[5].x = fmaf(fB.y, w.x, acc[5].x); acc[5].y = fmaf(fB.y, w.y, acc[5].y);
            acc[5].z = fmaf(fB.y, w.z, acc[5].z); acc[5].w = fmaf(fB.y, w.w, acc[5].w);
            acc[6].x = fmaf(fB.z, w.x, acc[6].x); acc[6].y = fmaf(fB.z, w.y, acc[6].y);
            acc[6].z = fmaf(fB.z, w.z, acc[6].z); acc[6].w = fmaf(fB.z, w.w, acc[6].w);
            acc[7].x = fmaf(fB.w, w.x, acc[7].x); acc[7].y = fmaf(fB.w, w.y, acc[7].y);
            acc[7].z = fmaf(fB.w, w.z, acc[7].z); acc[7].w = fmaf(fB.w, w.w, acc[7].w);
        }
        __syncthreads();
    }
    float4 b4 = *(const float4*)&bf[c0];
    float4* out4 = (float4*)g_pf;
#pragma unroll
    for (int r = 0; r < 8; r++) {
        float4 v = acc[r];
        v.x += b4.x; v.y += b4.y; v.z += b4.z; v.w += b4.w;
        out4[(size_t)(row0 + r0 + r)*64 + tx] = v;
    }
}

// ======================================================================
// Fused binning: count -> scan -> scatter, ONE block, smem counters.
// ======================================================================
__global__ __launch_bounds__(1024) void bin_all_kernel(const float* __restrict__ pc)
{
    __shared__ int scnt[NCELLS];   // 16 KB
    __shared__ int wsum[32];
    const int t = threadIdx.x;
    const float2* __restrict__ pc2 = (const float2*)pc;

    for (int i = t; i < NCELLS; i += 1024) scnt[i] = 0;
    __syncthreads();

    for (int n = t; n < NPTS; n += 1024) {
        float2 p = pc2[n];
        atomicAdd(&scnt[cell_of(p.x, p.y)], 1);
    }
    __syncthreads();

    int v[4], s = 0;
#pragma unroll
    for (int i = 0; i < 4; i++) { v[i] = scnt[t*4 + i]; s += v[i]; }
    const int lane = t & 31, wid = t >> 5;
    int incl = s;
#pragma unroll
    for (int o = 1; o < 32; o <<= 1) {
        int u = __shfl_up_sync(FULLMASK, incl, o);
        if (lane >= o) incl += u;
    }
    if (lane == 31) wsum[wid] = incl;
    __syncthreads();
    if (wid == 0) {
        int ws = wsum[lane];
#pragma unroll
        for (int o = 1; o < 32; o <<= 1) {
            int u = __shfl_up_sync(FULLMASK, ws, o);
            if (lane >= o) ws += u;
        }
        wsum[lane] = ws;
    }
    __syncthreads();
    int run = (wid > 0 ? wsum[wid-1] : 0) + incl - s;
    int starts[4];
#pragma unroll
    for (int i = 0; i < 4; i++) {
        starts[i] = run;
        g_start[t*4 + i] = run;
        run += v[i];
    }
    if (t == 1023) g_start[NCELLS] = run;
    __syncthreads();
#pragma unroll
    for (int i = 0; i < 4; i++) scnt[t*4 + i] = starts[i];
    __syncthreads();

    for (int n = t; n < NPTS; n += 1024) {
        float2 p = pc2[n];
        int pos = atomicAdd(&scnt[cell_of(p.x, p.y)], 1);
        g_pts[pos] = make_float4(p.x, p.y, sum_sq(p.x, p.y), __int_as_float(n));
    }
}

// ======================================================================
// Kernel: exact KNN (K=32), WARP PER GRID POINT, register top-32.
// Maintains a sorted (dist2,idx) top-32 (one key/lane) via warp bitonic
// sort+merge. Exact: retries with R2*=2 until worst_d <= R2.
// dist2 arithmetic bit-matches the reference.
// ======================================================================
__global__ __launch_bounds__(256) void knn_kernel()
{
    const int t    = threadIdx.x;
    const int lane = t & 31;
    const int g    = blockIdx.x * GPB + (t >> 5);

    const int wx = g % WW, hy = g / WW;
    const float gx = grid_coord(wx), gy = grid_coord(hy);
    const float g2 = sum_sq(gx, gy);

    // initial radius: E[candidates in disk] ~ 50; boost near boundary (clip)
    float R2 = 8.0e-4f;
    if (gx < 0.03f || gx > 0.97f) R2 *= 2.0f;
    if (gy < 0.03f || gy > 0.97f) R2 *= 2.0f;

    unsigned long long top = SENT;
    for (int iter = 0; iter < 16; iter++) {
        top = SENT;
        float R = sqrtf(R2);
        int cx0 = max(0,    (int)floorf((gx - R) * NC));
        int cx1 = min(NC-1, (int)floorf((gx + R) * NC));
        int cy0 = max(0,    (int)floorf((gy - R) * NC));
        int cy1 = min(NC-1, (int)floorf((gy + R) * NC));

        for (int cy = cy0; cy <= cy1; cy++) {
            int b = __ldg(&g_start[cy*NC + cx0]);
            int e = __ldg(&g_start[cy*NC + cx1 + 1]);
            for (int base = b; base < e; base += 32) {
                int j = base + lane;
                unsigned long long key = SENT;
                if (j < e) {
                    float4 p = g_pts[j];
                    float m = dot_ref(gx, gy, p.x, p.y);
                    float d = dist2_ref(g2, m, p.z);
                    key = ((unsigned long long)fkey(d) << 32)
                        | (unsigned int)__float_as_int(p.w);
                }
                unsigned long long worst = __shfl_sync(FULLMASK, top, 31);
                if (__any_sync(FULLMASK, key < worst)) {
                    key = wsort32(key, lane);                            // asc
                    unsigned long long rev = __shfl_sync(FULLMASK, key, 31 - lane);
                    unsigned long long mk  = top < rev ? top : rev;      // bitonic
                    top = wmerge32(mk, lane);                            // asc
                }
            }
        }
        unsigned long long worst = __shfl_sync(FULLMASK, top, 31);
        if ((unsigned int)(worst >> 32) <= fkey(R2)) break;   // 32 found, all <= R2
        R2 *= 2.0f;
    }
    g_knn[g*KNN + lane] = (int)(unsigned int)(top & 0xffffffffull);
}

// ======================================================================
// Kernel: attention MLP + softmax + weighted gather.  [R7/R8-proven]
// WARP PER GRID POINT. 8 warps/block.
// ======================================================================
__global__ __launch_bounds__(256) void attn_gather_kernel(
    const float* __restrict__ pc,
    const float* __restrict__ W1, const float* __restrict__ b1,
    const float* __restrict__ W2, const float* __restrict__ b2)
{
    __shared__ __align__(16) float4 sW14[HID];   // (w0,w1,w2,b1)
    __shared__ float  sW2[HID];
    __shared__ float  swt[GPB][KNN];
    __shared__ int    soff[GPB][KNN];            // float4 row offsets

    const int t = threadIdx.x;
    const int w = t >> 5;
    const int l = t & 31;
    const int g = blockIdx.x * GPB + w;

    if (t < HID) {
        sW14[t] = make_float4(W1[t*3], W1[t*3+1], W1[t*3+2], b1[t]);
        sW2[t]  = W2[t];
    }

    const int wx = g % WW, hy = g / WW;
    const float gx = grid_coord(wx), gy = grid_coord(hy);

    const int id = g_knn[g*KNN + l];
    const float px = pc[2*id], py = pc[2*id+1];
    const float dx = __fsub_rn(gx, px), dy = __fsub_rn(gy, py);
    const float dd = sqrtf(sum_sq(dx, dy));
    __syncthreads();

    float acc = 0.0f;
#pragma unroll 16
    for (int j = 0; j < HID; j++) {
        float4 wv = sW14[j];
        float pre = fmaf(wv.x, dx, fmaf(wv.y, dy, fmaf(wv.z, dd, wv.w)));
        float ge  = 0.5f * pre * (1.0f + erff(pre * 0.70710678118654752f));
        acc = fmaf(sW2[j], ge, acc);
    }
    float logit = acc + b2[0];

    float m = logit;
#pragma unroll
    for (int o = 16; o >= 1; o >>= 1) m = fmaxf(m, __shfl_xor_sync(FULLMASK, m, o));
    float e = expf(logit - m);
    float s = e;
#pragma unroll
    for (int o = 16; o >= 1; o >>= 1) s += __shfl_xor_sync(FULLMASK, s, o);
    swt[w][l]  = e / s;
    soff[w][l] = id * (GD/4);
    __syncwarp();

    const float4* __restrict__ pf4 = (const float4*)g_pf;
    float4 a0 = make_float4(0.f,0.f,0.f,0.f);
    float4 a1 = make_float4(0.f,0.f,0.f,0.f);
#pragma unroll 8
    for (int k = 0; k < KNN; k++) {
        float wk = swt[w][k];
        int   ro = soff[w][k];
        float4 v0 = pf4[(size_t)ro + l];
        float4 v1 = pf4[(size_t)ro + 32 + l];
        a0.x = fmaf(wk, v0.x, a0.x); a0.y = fmaf(wk, v0.y, a0.y);
        a0.z = fmaf(wk, v0.z, a0.z); a0.w = fmaf(wk, v0.w, a0.w);
        a1.x = fmaf(wk, v1.x, a1.x); a1.y = fmaf(wk, v1.y, a1.y);
        a1.z = fmaf(wk, v1.z, a1.z); a1.w = fmaf(wk, v1.w, a1.w);
    }
    float4* mid4 = (float4*)g_mid;
    mid4[(size_t)g*(GD/4) + l]      = a0;
    mid4[(size_t)g*(GD/4) + 32 + l] = a1;
}

// ======================================================================
// Kernel: out = mid @ W_out^T + b_out, then LayerNorm.   [R5/R8-proven]
// ======================================================================
__global__ __launch_bounds__(256) void outproj_ln_kernel(
    const float* __restrict__ Wo,   // [256,256]
    const float* __restrict__ bo,
    const float* __restrict__ lng,
    const float* __restrict__ lnb,
    float* __restrict__ out)
{
    __shared__ __align__(16) float sW[32*260];   // [kk][c]; reused as sOut [r][c]
    __shared__ __align__(16) float sF[32*36];    // [kk][r]
    __shared__ float sMu[32], sRs[32];

    const int t    = threadIdx.x;
    const int row0 = blockIdx.x * 32;
    const int ty   = t >> 6;
    const int tx   = t & 63;
    const int r0   = ty * 8;
    const int c0   = tx * 4;

    const float4* Wo4  = (const float4*)Wo;
    const float4* mid4 = (const float4*)g_mid;

    float4 acc[8];
#pragma unroll
    for (int r = 0; r < 8; r++) acc[r] = make_float4(0.f,0.f,0.f,0.f);

    for (int kt = 0; kt < GD; kt += 32) {
#pragma unroll
        for (int i = 0; i < 8; i++) {
            int lin = i * 256 + t;
            int kk4 = lin & 7;
            int c   = lin >> 3;
            float4 v = Wo4[c*64 + (kt>>2) + kk4];
            sW[(kk4*4+0)*260 + c] = v.x;
            sW[(kk4*4+1)*260 + c] = v.y;
            sW[(kk4*4+2)*260 + c] = v.z;
            sW[(kk4*4+3)*260 + c] = v.w;
        }
        {
            int kk4 = t & 7;
            int r   = t >> 3;
            float4 v = mid4[(size_t)(row0 + r)*64 + (kt>>2) + kk4];
            sF[(kk4*4+0)*36 + r] = v.x;
            sF[(kk4*4+1)*36 + r] = v.y;
            sF[(kk4*4+2)*36 + r] = v.z;
            sF[(kk4*4+3)*36 + r] = v.w;
        }
        __syncthreads();
#pragma unroll
        for (int kk = 0; kk < 32; kk++) {
            float4 w  = *(const float4*)&sW[kk*260 + c0];
            float4 fA = *(const float4*)&sF[kk*36 + r0];
            float4 fB = *(const float4*)&sF[kk*36 + r0 + 4];
            acc[0].x = fmaf(fA.x, w.x, acc[0].x); acc[0].y = fmaf(fA.x, w.y, acc[0].y);
            acc[0].z = fmaf(fA.x, w.z, acc[0].z); acc[0].w = fmaf(fA.x, w.w, acc[0].w);
            acc[1].x = fmaf(fA.y, w.x, acc[1].x); acc[1].y = fmaf(fA.y, w.y, acc[1].y);
            acc[1].z = fmaf(fA.y, w.z, acc[1].z); acc[1].w = fmaf(fA.y, w.w, acc[1].w);
            acc[2].x = fmaf(fA.z, w.x, acc[2].x); acc[2].y = fmaf(fA.z, w.y, acc[2].y);
            acc[2].z = fmaf(fA.z, w.z, acc[2].z); acc[2].w = fmaf(fA.z, w.w, acc[2].w);
            acc[3].x = fmaf(fA.w, w.x, acc[3].x); acc[3].y = fmaf(fA.w, w.y, acc[3].y);
            acc[3].z = fmaf(fA.w, w.z, acc[3].z); acc[3].w = fmaf(fA.w, w.w, acc[3].w);
            acc[4].x = fmaf(fB.x, w.x, acc[4].x); acc[4].y = fmaf(fB.x, w.y, acc[4].y);
            acc[4].z = fmaf(fB.x, w.z, acc[4].z); acc[4].w = fmaf(fB.x, w.w, acc[4].w);
            acc[5].x = fmaf(fB.y, w.x, acc[5].x); acc[5].y = fmaf(fB.y, w.y, acc[5].y);
            acc[5].z = fmaf(fB.y, w.z, acc[5].z); acc[5].w = fmaf(fB.y, w.w, acc[5].w);
            acc[6].x = fmaf(fB.z, w.x, acc[6].x); acc[6].y = fmaf(fB.z, w.y, acc[6].y);
            acc[6].z = fmaf(fB.z, w.z, acc[6].z); acc[6].w = fmaf(fB.z, w.w, acc[6].w);
            acc[7].x = fmaf(fB.w, w.x, acc[7].x); acc[7].y = fmaf(fB.w, w.y, acc[7].y);
            acc[7].z = fmaf(fB.w, w.z, acc[7].z); acc[7].w = fmaf(fB.w, w.w, acc[7].w);
        }
        __syncthreads();
    }

    float4 b4 = *(const float4*)&bo[c0];
#pragma unroll
    for (int r = 0; r < 8; r++) {
        float4 v = acc[r];
        v.x += b4.x; v.y += b4.y; v.z += b4.z; v.w += b4.w;
        *(float4*)&sW[(r0 + r)*260 + c0] = v;
    }
    __syncthreads();

    const int lane = t & 31, wid = t >> 5;
    for (int r = wid; r < 32; r += 8) {
        float s = 0.0f;
#pragma unroll
        for (int i = lane; i < GD; i += 32) s += sW[r*260 + i];
#pragma unroll
        for (int o = 16; o >= 1; o >>= 1) s += __shfl_xor_sync(FULLMASK, s, o);
        float mu = s * (1.0f / GD);
        float v = 0.0f;
#pragma unroll
        for (int i = lane; i < GD; i += 32) {
            float d = sW[r*260 + i] - mu;
            v = fmaf(d, d, v);
        }
#pragma unroll
        for (int o = 16; o >= 1; o >>= 1) v += __shfl_xor_sync(FULLMASK, v, o);
        if (lane == 0) { sMu[r] = mu; sRs[r] = rsqrtf(v * (1.0f / GD) + EPSLN); }
    }
    __syncthreads();

    float4 g4 = *(const float4*)&lng[c0];
    float4 be4 = *(const float4*)&lnb[c0];
    float4* out4 = (float4*)out;
#pragma unroll
    for (int r = 0; r < 8; r++) {
        int rr = r0 + r;
        float mu = sMu[rr], rs = sRs[rr];
        float4 v = *(const float4*)&sW[rr*260 + c0];
        v.x = (v.x - mu) * rs * g4.x + be4.x;
        v.y = (v.y - mu) * rs * g4.y + be4.y;
        v.z = (v.z - mu) * rs * g4.z + be4.z;
        v.w = (v.w - mu) * rs * g4.w + be4.w;
        out4[(size_t)(row0 + rr)*64 + tx] = v;
    }
}

// ======================================================================
// launcher
// ======================================================================
extern "C" void kernel_launch(void* const* d_in, const int* in_sizes, int n_in,
                              void* d_out, int out_size)
{
    const float* point_features = (const float*)d_in[0];
    const float* point_coords   = (const float*)d_in[1];
    const float* W_feat         = (const float*)d_in[2];
    const float* b_feat         = (const float*)d_in[3];
    const float* W1             = (const float*)d_in[4];
    const float* b1             = (const float*)d_in[5];
    const float* W2             = (const float*)d_in[6];
    const float* b2             = (const float*)d_in[7];
    const float* W_out          = (const float*)d_in[8];
    const float* b_out          = (const float*)d_in[9];
    const float* ln_g           = (const float*)d_in[10];
    const float* ln_b           = (const float*)d_in[11];
    float* out = (float*)d_out;

    // 1. fused binning
    bin_all_kernel<<<1, 1024>>>(point_coords);

    // 2. feature projection (R5 reg-tiled)
    pf_kernel<<<NPTS/32, 256>>>(point_features, W_feat, b_feat);

    // 3. exact KNN (warp per grid point, register top-32)
    knn_kernel<<<G/GPB, 256>>>();

    // 4. attention + gather (warp per grid point)
    attn_gather_kernel<<<G/GPB, 256>>>(point_coords, W1, b1, W2, b2);

    // 5. output projection + layernorm (R5 reg-tiled)
    outproj_ln_kernel<<<G/32, 256>>>(W_out, b_out, ln_g, ln_b, out);
}

// round 10
// speedup vs baseline: 1.6776x; 1.0287x over previous
#include <cuda_runtime.h>
#include <cuda_bf16.h>
#include <math.h>
#include <float.h>

// ---------------- problem constants (fixed dataset) ----------------
#define NPTS    20000
#define PD      64          // point feature dim
#define GD      256         // grid feature dim
#define HH      96
#define WW      96
#define G       (HH*WW)     // 9216 grid points
#define KNN     32
#define HID     64
#define NC      64          // bin grid 64x64
#define NCELLS  (NC*NC)
#define EPSLN   1e-5f
#define GPB     8           // grid points per attn/knn block (8 warps)

// step = f32(1/95), exactly as JAX f32 linspace computes it
#define STEP    (1.0f/95.0f)

#define FULLMASK 0xffffffffu
#define SENT     0xffffffffffffffffull

// ---------------- scratch (device globals, no allocations) ----------------
__device__ float  g_pf[NPTS*GD];       // projected point features (20.5 MB)
__device__ int    g_start[NCELLS+1];
__device__ float4 g_pts[NPTS];         // (px, py, p2, idx-as-float), binned order
__device__ int    g_knn[G*KNN];
__device__ float  g_mid[G*GD];         // aggregated features before out-proj

// exact-rounding helpers for the KNN distance path (must bit-match reference)
__device__ __forceinline__ float grid_coord(int i) {
    return __fmul_rn((float)i, STEP);
}
__device__ __forceinline__ float sum_sq(float x, float y) {
    return __fadd_rn(__fmul_rn(x, x), __fmul_rn(y, y));
}
__device__ __forceinline__ float dot_ref(float gx, float gy, float px, float py) {
    return __fadd_rn(__fmul_rn(gx, px), __fmul_rn(gy, py));
}
__device__ __forceinline__ float dist2_ref(float g2, float m, float p2) {
    return __fadd_rn(__fsub_rn(g2, __fmul_rn(2.0f, m)), p2);
}
__device__ __forceinline__ int cell_of(float px, float py) {
    int cx = (int)(px * NC); cx = min(max(cx, 0), NC-1);
    int cy = (int)(py * NC); cy = min(max(cy, 0), NC-1);
    return cy * NC + cx;
}
// monotone float -> uint mapping (handles tiny negative fp dist2)
__device__ __forceinline__ unsigned int fkey(float d) {
    unsigned int u = __float_as_uint(d);
    return (u & 0x80000000u) ? ~u : (u | 0x80000000u);
}

// warp bitonic full sort, ascending across lanes (15 stages)
__device__ __forceinline__ unsigned long long wsort32(unsigned long long key, int lane) {
#pragma unroll
    for (int k = 2; k <= 32; k <<= 1) {
#pragma unroll
        for (int j = k >> 1; j > 0; j >>= 1) {
            unsigned long long p = __shfl_xor_sync(FULLMASK, key, j);
            bool up      = ((lane & k) == 0);
            bool keepMin = (((lane & j) == 0) == up);
            unsigned long long lo = key < p ? key : p;
            unsigned long long hi = key < p ? p : key;
            key = keepMin ? lo : hi;
        }
    }
    return key;
}
// clean a 32-length bitonic sequence into ascending order (5 stages)
__device__ __forceinline__ unsigned long long wmerge32(unsigned long long key, int lane) {
#pragma unroll
    for (int j = 16; j > 0; j >>= 1) {
        unsigned long long p = __shfl_xor_sync(FULLMASK, key, j);
        unsigned long long lo = key < p ? key : p;
        unsigned long long hi = key < p ? p : key;
        key = ((lane & j) == 0) ? lo : hi;
    }
    return key;
}

// ======================================================================
// Kernel 1: pf = feat @ W_feat^T + b_feat   [20000 x 256]   [R5/R8-proven]
// ======================================================================
__global__ __launch_bounds__(256) void pf_kernel(
    const float* __restrict__ feat,   // [NPTS,64]
    const float* __restrict__ Wf,     // [256,64]
    const float* __restrict__ bf)     // [256]
{
    __shared__ __align__(16) float sW[32*260];   // [kk][c]
    __shared__ __align__(16) float sF[32*36];    // [kk][r]
    const int t    = threadIdx.x;
    const int row0 = blockIdx.x * 32;
    const int ty   = t >> 6;
    const int tx   = t & 63;
    const int r0   = ty * 8;
    const int c0   = tx * 4;

    const float4* feat4 = (const float4*)feat;
    const float4* Wf4   = (const float4*)Wf;

    float4 acc[8];
#pragma unroll
    for (int r = 0; r < 8; r++) acc[r] = make_float4(0.f,0.f,0.f,0.f);

    for (int kt = 0; kt < PD; kt += 32) {
#pragma unroll
        for (int i = 0; i < 8; i++) {
            int lin = i * 256 + t;
            int kk4 = lin & 7;
            int c   = lin >> 3;
            float4 v = Wf4[c*16 + (kt>>2) + kk4];
            sW[(kk4*4+0)*260 + c] = v.x;
            sW[(kk4*4+1)*260 + c] = v.y;
            sW[(kk4*4+2)*260 + c] = v.z;
            sW[(kk4*4+3)*260 + c] = v.w;
        }
        {
            int kk4 = t & 7;
            int r   = t >> 3;
            float4 v = feat4[(size_t)(row0 + r)*16 + (kt>>2) + kk4];
            sF[(kk4*4+0)*36 + r] = v.x;
            sF[(kk4*4+1)*36 + r] = v.y;
            sF[(kk4*4+2)*36 + r] = v.z;
            sF[(kk4*4+3)*36 + r] = v.w;
        }
        __syncthreads();
#pragma unroll
        for (int kk = 0; kk < 32; kk++) {
            float4 w  = *(const float4*)&sW[kk*260 + c0];
            float4 fA = *(const float4*)&sF[kk*36 + r0];
            float4 fB = *(const float4*)&sF[kk*36 + r0 + 4];
            acc[0].x = fmaf(fA.x, w.x, acc[0].x); acc[0].y = fmaf(fA.x, w.y, acc[0].y);
            acc[0].z = fmaf(fA.x, w.z, acc[0].z); acc[0].w = fmaf(fA.x, w.w, acc[0].w);
            acc[1].x = fmaf(fA.y, w.x, acc[1].x); acc[1].y = fmaf(fA.y, w.y, acc[1].y);
            acc[1].z = fmaf(fA.y, w.z, acc[1].z); acc[1].w = fmaf(fA.y, w.w, acc[1].w);
            acc[2].x = fmaf(fA.z, w.x, acc[2].x); acc[2].y = fmaf(fA.z, w.y, acc[2].y);
            acc[2].z = fmaf(fA.z, w.z, acc[2].z); acc[2].w = fmaf(fA.z, w.w, acc[2].w);
            acc[3].x = fmaf(fA.w, w.x, acc[3].x); acc[3].y = fmaf(fA.w, w.y, acc[3].y);
            acc[3].z = fmaf(fA.w, w.z, acc[3].z); acc[3].w = fmaf(fA.w, w.w, acc[3].w);
            acc[4].x = fmaf(fB.x, w.x, acc[4].x); acc[4].y = fmaf(fB.x, w.y, acc[4].y);
            acc[4].z = fmaf(fB.x, w.z, acc[4].z); acc[4].w = fmaf(fB.x, w.w, acc[4].w);
            acc[5].x = fmaf(fB.y, w.x, acc[5].x); acc[5].y = fmaf(fB.y, w.y, acc[5].y);
            acc[5].z = fmaf(fB.y, w.z, acc[5].z); acc[5].w = fmaf(fB.y, w.w, acc[5].w);
            acc[6].x = fmaf(fB.z, w.x, acc[6].x); acc[6].y = fmaf(fB.z, w.y, acc[6].y);
            acc[6].z = fmaf(fB.z, w.z, acc[6].z); acc[6].w = fmaf(fB.z, w.w, acc[6].w);
            acc[7].x = fmaf(fB.w, w.x, acc[7].x); acc[7].y = fmaf(fB.w, w.y, acc[7].y);
            acc[7].z = fmaf(fB.w, w.z, acc[7].z); acc[7].w = fmaf(fB.w, w.w, acc[7].w);
        }
        __syncthreads();
    }
    float4 b4 = *(const float4*)&bf[c0];
    float4* out4 = (float4*)g_pf;
#pragma unroll
    for (int r = 0; r < 8; r++) {
        float4 v = acc[r];
        v.x += b4.x; v.y += b4.y; v.z += b4.z; v.w += b4.w;
        out4[(size_t)(row0 + r0 + r)*64 + tx] = v;
    }
}

// ======================================================================
// Fused binning: count -> scan -> scatter, ONE block, smem counters.
// ======================================================================
__global__ __launch_bounds__(1024) void bin_all_kernel(const float* __restrict__ pc)
{
    __shared__ int scnt[NCELLS];   // 16 KB
    __shared__ int wsum[32];
    const int t = threadIdx.x;
    const float2* __restrict__ pc2 = (const float2*)pc;

    for (int i = t; i < NCELLS; i += 1024) scnt[i] = 0;
    __syncthreads();

    for (int n = t; n < NPTS; n += 1024) {
        float2 p = pc2[n];
        atomicAdd(&scnt[cell_of(p.x, p.y)], 1);
    }
    __syncthreads();

    int v[4], s = 0;
#pragma unroll
    for (int i = 0; i < 4; i++) { v[i] = scnt[t*4 + i]; s += v[i]; }
    const int lane = t & 31, wid = t >> 5;
    int incl = s;
#pragma unroll
    for (int o = 1; o < 32; o <<= 1) {
        int u = __shfl_up_sync(FULLMASK, incl, o);
        if (lane >= o) incl += u;
    }
    if (lane == 31) wsum[wid] = incl;
    __syncthreads();
    if (wid == 0) {
        int ws = wsum[lane];
#pragma unroll
        for (int o = 1; o < 32; o <<= 1) {
            int u = __shfl_up_sync(FULLMASK, ws, o);
            if (lane >= o) ws += u;
        }
        wsum[lane] = ws;
    }
    __syncthreads();
    int run = (wid > 0 ? wsum[wid-1] : 0) + incl - s;
    int starts[4];
#pragma unroll
    for (int i = 0; i < 4; i++) {
        starts[i] = run;
        g_start[t*4 + i] = run;
        run += v[i];
    }
    if (t == 1023) g_start[NCELLS] = run;
    __syncthreads();
#pragma unroll
    for (int i = 0; i < 4; i++) scnt[t*4 + i] = starts[i];
    __syncthreads();

    for (int n = t; n < NPTS; n += 1024) {
        float2 p = pc2[n];
        int pos = atomicAdd(&scnt[cell_of(p.x, p.y)], 1);
        g_pts[pos] = make_float4(p.x, p.y, sum_sq(p.x, p.y), __int_as_float(n));
    }
}

// ======================================================================
// Kernel: exact KNN (K=32), WARP PER GRID POINT, register top-32. [R9]
// ======================================================================
__global__ __launch_bounds__(256) void knn_kernel()
{
    const int t    = threadIdx.x;
    const int lane = t & 31;
    const int g    = blockIdx.x * GPB + (t >> 5);

    const int wx = g % WW, hy = g / WW;
    const float gx = grid_coord(wx), gy = grid_coord(hy);
    const float g2 = sum_sq(gx, gy);

    float R2 = 8.0e-4f;
    if (gx < 0.03f || gx > 0.97f) R2 *= 2.0f;
    if (gy < 0.03f || gy > 0.97f) R2 *= 2.0f;

    unsigned long long top = SENT;
    for (int iter = 0; iter < 16; iter++) {
        top = SENT;
        float R = sqrtf(R2);
        int cx0 = max(0,    (int)floorf((gx - R) * NC));
        int cx1 = min(NC-1, (int)floorf((gx + R) * NC));
        int cy0 = max(0,    (int)floorf((gy - R) * NC));
        int cy1 = min(NC-1, (int)floorf((gy + R) * NC));

        for (int cy = cy0; cy <= cy1; cy++) {
            int b = __ldg(&g_start[cy*NC + cx0]);
            int e = __ldg(&g_start[cy*NC + cx1 + 1]);
            for (int base = b; base < e; base += 32) {
                int j = base + lane;
                unsigned long long key = SENT;
                if (j < e) {
                    float4 p = g_pts[j];
                    float m = dot_ref(gx, gy, p.x, p.y);
                    float d = dist2_ref(g2, m, p.z);
                    key = ((unsigned long long)fkey(d) << 32)
                        | (unsigned int)__float_as_int(p.w);
                }
                unsigned long long worst = __shfl_sync(FULLMASK, top, 31);
                if (__any_sync(FULLMASK, key < worst)) {
                    key = wsort32(key, lane);                            // asc
                    unsigned long long rev = __shfl_sync(FULLMASK, key, 31 - lane);
                    unsigned long long mk  = top < rev ? top : rev;      // bitonic
                    top = wmerge32(mk, lane);                            // asc
                }
            }
        }
        unsigned long long worst = __shfl_sync(FULLMASK, top, 31);
        if ((unsigned int)(worst >> 32) <= fkey(R2)) break;
        R2 *= 2.0f;
    }
    g_knn[g*KNN + lane] = (int)(unsigned int)(top & 0xffffffffull);
}

// ======================================================================
// Kernel: attention MLP + softmax + weighted gather.  [R7/R8-proven]
// ======================================================================
__global__ __launch_bounds__(256) void attn_gather_kernel(
    const float* __restrict__ pc,
    const float* __restrict__ W1, const float* __restrict__ b1,
    const float* __restrict__ W2, const float* __restrict__ b2)
{
    __shared__ __align__(16) float4 sW14[HID];   // (w0,w1,w2,b1)
    __shared__ float  sW2[HID];
    __shared__ float  swt[GPB][KNN];
    __shared__ int    soff[GPB][KNN];            // float4 row offsets

    const int t = threadIdx.x;
    const int w = t >> 5;
    const int l = t & 31;
    const int g = blockIdx.x * GPB + w;

    if (t < HID) {
        sW14[t] = make_float4(W1[t*3], W1[t*3+1], W1[t*3+2], b1[t]);
        sW2[t]  = W2[t];
    }

    const int wx = g % WW, hy = g / WW;
    const float gx = grid_coord(wx), gy = grid_coord(hy);

    const int id = g_knn[g*KNN + l];
    const float px = pc[2*id], py = pc[2*id+1];
    const float dx = __fsub_rn(gx, px), dy = __fsub_rn(gy, py);
    const float dd = sqrtf(sum_sq(dx, dy));
    __syncthreads();

    float acc = 0.0f;
#pragma unroll 16
    for (int j = 0; j < HID; j++) {
        float4 wv = sW14[j];
        float pre = fmaf(wv.x, dx, fmaf(wv.y, dy, fmaf(wv.z, dd, wv.w)));
        float ge  = 0.5f * pre * (1.0f + erff(pre * 0.70710678118654752f));
        acc = fmaf(sW2[j], ge, acc);
    }
    float logit = acc + b2[0];

    float m = logit;
#pragma unroll
    for (int o = 16; o >= 1; o >>= 1) m = fmaxf(m, __shfl_xor_sync(FULLMASK, m, o));
    float e = expf(logit - m);
    float s = e;
#pragma unroll
    for (int o = 16; o >= 1; o >>= 1) s += __shfl_xor_sync(FULLMASK, s, o);
    swt[w][l]  = e / s;
    soff[w][l] = id * (GD/4);
    __syncwarp();

    const float4* __restrict__ pf4 = (const float4*)g_pf;
    float4 a0 = make_float4(0.f,0.f,0.f,0.f);
    float4 a1 = make_float4(0.f,0.f,0.f,0.f);
#pragma unroll 8
    for (int k = 0; k < KNN; k++) {
        float wk = swt[w][k];
        int   ro = soff[w][k];
        float4 v0 = pf4[(size_t)ro + l];
        float4 v1 = pf4[(size_t)ro + 32 + l];
        a0.x = fmaf(wk, v0.x, a0.x); a0.y = fmaf(wk, v0.y, a0.y);
        a0.z = fmaf(wk, v0.z, a0.z); a0.w = fmaf(wk, v0.w, a0.w);
        a1.x = fmaf(wk, v1.x, a1.x); a1.y = fmaf(wk, v1.y, a1.y);
        a1.z = fmaf(wk, v1.z, a1.z); a1.w = fmaf(wk, v1.w, a1.w);
    }
    float4* mid4 = (float4*)g_mid;
    mid4[(size_t)g*(GD/4) + l]      = a0;
    mid4[(size_t)g*(GD/4) + 32 + l] = a1;
}

// ======================================================================
// Kernel: out = mid @ W_out^T + b_out, then LayerNorm.   [R5/R8-proven]
// ======================================================================
__global__ __launch_bounds__(256) void outproj_ln_kernel(
    const float* __restrict__ Wo,   // [256,256]
    const float* __restrict__ bo,
    const float* __restrict__ lng,
    const float* __restrict__ lnb,
    float* __restrict__ out)
{
    __shared__ __align__(16) float sW[32*260];   // [kk][c]; reused as sOut [r][c]
    __shared__ __align__(16) float sF[32*36];    // [kk][r]
    __shared__ float sMu[32], sRs[32];

    const int t    = threadIdx.x;
    const int row0 = blockIdx.x * 32;
    const int ty   = t >> 6;
    const int tx   = t & 63;
    const int r0   = ty * 8;
    const int c0   = tx * 4;

    const float4* Wo4  = (const float4*)Wo;
    const float4* mid4 = (const float4*)g_mid;

    float4 acc[8];
#pragma unroll
    for (int r = 0; r < 8; r++) acc[r] = make_float4(0.f,0.f,0.f,0.f);

    for (int kt = 0; kt < GD; kt += 32) {
#pragma unroll
        for (int i = 0; i < 8; i++) {
            int lin = i * 256 + t;
            int kk4 = lin & 7;
            int c   = lin >> 3;
            float4 v = Wo4[c*64 + (kt>>2) + kk4];
            sW[(kk4*4+0)*260 + c] = v.x;
            sW[(kk4*4+1)*260 + c] = v.y;
            sW[(kk4*4+2)*260 + c] = v.z;
            sW[(kk4*4+3)*260 + c] = v.w;
        }
        {
            int kk4 = t & 7;
            int r   = t >> 3;
            float4 v = mid4[(size_t)(row0 + r)*64 + (kt>>2) + kk4];
            sF[(kk4*4+0)*36 + r] = v.x;
            sF[(kk4*4+1)*36 + r] = v.y;
            sF[(kk4*4+2)*36 + r] = v.z;
            sF[(kk4*4+3)*36 + r] = v.w;
        }
        __syncthreads();
#pragma unroll
        for (int kk = 0; kk < 32; kk++) {
            float4 w  = *(const float4*)&sW[kk*260 + c0];
            float4 fA = *(const float4*)&sF[kk*36 + r0];
            float4 fB = *(const float4*)&sF[kk*36 + r0 + 4];
            acc[0].x = fmaf(fA.x, w.x, acc[0].x); acc[0].y = fmaf(fA.x, w.y, acc[0].y);
            acc[0].z = fmaf(fA.x, w.z, acc[0].z); acc[0].w = fmaf(fA.x, w.w, acc[0].w);
            acc[1].x = fmaf(fA.y, w.x, acc[1].x); acc[1].y = fmaf(fA.y, w.y, acc[1].y);
            acc[1].z = fmaf(fA.y, w.z, acc[1].z); acc[1].w = fmaf(fA.y, w.w, acc[1].w);
            acc[2].x = fmaf(fA.z, w.x, acc[2].x); acc[2].y = fmaf(fA.z, w.y, acc[2].y);
            acc[2].z = fmaf(fA.z, w.z, acc[2].z); acc[2].w = fmaf(fA.z, w.w, acc[2].w);
            acc[3].x = fmaf(fA.w, w.x, acc[3].x); acc[3].y = fmaf(fA.w, w.y, acc[3].y);
            acc[3].z = fmaf(fA.w, w.z, acc[3].z); acc[3].w = fmaf(fA.w, w.w, acc[3].w);
            acc[4].x = fmaf(fB.x, w.x, acc[4].x); acc[4].y = fmaf(fB.x, w.y, acc[4].y);
            acc[4].z = fmaf(fB.x, w.z, acc[4].z); acc[4].w = fmaf(fB.x, w.w, acc[4].w);
            acc[5].x = fmaf(fB.y, w.x, acc[5].x); acc[5].y = fmaf(fB.y, w.y, acc[5].y);
            acc[5].z = fmaf(fB.y, w.z, acc[5].z); acc[5].w = fmaf(fB.y, w.w, acc[5].w);
            acc[6].x = fmaf(fB.z, w.x, acc[6].x); acc[6].y = fmaf(fB.z, w.y, acc[6].y);
            acc[6].z = fmaf(fB.z, w.z, acc[6].z); acc[6].w = fmaf(fB.z, w.w, acc[6].w);
            acc[7].x = fmaf(fB.w, w.x, acc[7].x); acc[7].y = fmaf(fB.w, w.y, acc[7].y);
            acc[7].z = fmaf(fB.w, w.z, acc[7].z); acc[7].w = fmaf(fB.w, w.w, acc[7].w);
        }
        __syncthreads();
    }

    float4 b4 = *(const float4*)&bo[c0];
#pragma unroll
    for (int r = 0; r < 8; r++) {
        float4 v = acc[r];
        v.x += b4.x; v.y += b4.y; v.z += b4.z; v.w += b4.w;
        *(float4*)&sW[(r0 + r)*260 + c0] = v;
    }
    __syncthreads();

    const int lane = t & 31, wid = t >> 5;
    for (int r = wid; r < 32; r += 8) {
        float s = 0.0f;
#pragma unroll
        for (int i = lane; i < GD; i += 32) s += sW[r*260 + i];
#pragma unroll
        for (int o = 16; o >= 1; o >>= 1) s += __shfl_xor_sync(FULLMASK, s, o);
        float mu = s * (1.0f / GD);
        float v = 0.0f;
#pragma unroll
        for (int i = lane; i < GD; i += 32) {
            float d = sW[r*260 + i] - mu;
            v = fmaf(d, d, v);
        }
#pragma unroll
        for (int o = 16; o >= 1; o >>= 1) v += __shfl_xor_sync(FULLMASK, v, o);
        if (lane == 0) { sMu[r] = mu; sRs[r] = rsqrtf(v * (1.0f / GD) + EPSLN); }
    }
    __syncthreads();

    float4 g4 = *(const float4*)&lng[c0];
    float4 be4 = *(const float4*)&lnb[c0];
    float4* out4 = (float4*)out;
#pragma unroll
    for (int r = 0; r < 8; r++) {
        int rr = r0 + r;
        float mu = sMu[rr], rs = sRs[rr];
        float4 v = *(const float4*)&sW[rr*260 + c0];
        v.x = (v.x - mu) * rs * g4.x + be4.x;
        v.y = (v.y - mu) * rs * g4.y + be4.y;
        v.z = (v.z - mu) * rs * g4.z + be4.z;
        v.w = (v.w - mu) * rs * g4.w + be4.w;
        out4[(size_t)(row0 + rr)*64 + tx] = v;
    }
}

// ======================================================================
// launcher — fork/join: pf runs concurrently with bin->knn.
// Event record/wait are graph-capturable; stream/event create are host ops.
// ======================================================================
extern "C" void kernel_launch(void* const* d_in, const int* in_sizes, int n_in,
                              void* d_out, int out_size)
{
    const float* point_features = (const float*)d_in[0];
    const float* point_coords   = (const float*)d_in[1];
    const float* W_feat         = (const float*)d_in[2];
    const float* b_feat         = (const float*)d_in[3];
    const float* W1             = (const float*)d_in[4];
    const float* b1             = (const float*)d_in[5];
    const float* W2             = (const float*)d_in[6];
    const float* b2             = (const float*)d_in[7];
    const float* W_out          = (const float*)d_in[8];
    const float* b_out          = (const float*)d_in[9];
    const float* ln_g           = (const float*)d_in[10];
    const float* ln_b           = (const float*)d_in[11];
    float* out = (float*)d_out;

    cudaStream_t s1;
    cudaStreamCreateWithFlags(&s1, cudaStreamNonBlocking);
    cudaEvent_t evFork, evJoin;
    cudaEventCreateWithFlags(&evFork, cudaEventDisableTiming);
    cudaEventCreateWithFlags(&evJoin, cudaEventDisableTiming);

    // fork: branch A (pf) on s1
    cudaEventRecord(evFork, 0);
    cudaStreamWaitEvent(s1, evFork, 0);
    pf_kernel<<<NPTS/32, 256, 0, s1>>>(point_features, W_feat, b_feat);
    cudaEventRecord(evJoin, s1);

    // branch B (bin -> knn) on the main (capture) stream
    bin_all_kernel<<<1, 1024>>>(point_coords);
    knn_kernel<<<G/GPB, 256>>>();

    // join: attn needs both pf and knn
    cudaStreamWaitEvent(0, evJoin, 0);
    attn_gather_kernel<<<G/GPB, 256>>>(point_coords, W1, b1, W2, b2);
    outproj_ln_kernel<<<G/32, 256>>>(W_out, b_out, ln_g, ln_b, out);

    cudaEventDestroy(evFork);
    cudaEventDestroy(evJoin);
    cudaStreamDestroy(s1);
}

// round 11
// speedup vs baseline: 1.6855x; 1.0047x over previous
#include <cuda_runtime.h>
#include <cuda_bf16.h>
#include <math.h>
#include <float.h>

// ---------------- problem constants (fixed dataset) ----------------
#define NPTS    20000
#define PD      64          // point feature dim
#define GD      256         // grid feature dim
#define HH      96
#define WW      96
#define G       (HH*WW)     // 9216 grid points
#define KNN     32
#define HID     64
#define NC      64          // bin grid 64x64
#define NCELLS  (NC*NC)
#define EPSLN   1e-5f
#define GPB     8           // grid points per attn/knn block (8 warps)

// step = f32(1/95), exactly as JAX f32 linspace computes it
#define STEP    (1.0f/95.0f)

#define FULLMASK 0xffffffffu
#define SENT     0xffffffffffffffffull

typedef unsigned long long ull;

// ---------------- scratch (device globals, no allocations) ----------------
__device__ float  g_pf[NPTS*GD];       // projected point features (20.5 MB)
__device__ int    g_start[NCELLS+1];
__device__ float4 g_pts[NPTS];         // (px, py, p2, idx-as-float), binned order
__device__ int    g_knn[G*KNN];
__device__ float  g_mid[G*GD];         // aggregated features before out-proj

// exact-rounding helpers for the KNN distance path (must bit-match reference)
__device__ __forceinline__ float grid_coord(int i) {
    return __fmul_rn((float)i, STEP);
}
__device__ __forceinline__ float sum_sq(float x, float y) {
    return __fadd_rn(__fmul_rn(x, x), __fmul_rn(y, y));
}
__device__ __forceinline__ float dot_ref(float gx, float gy, float px, float py) {
    return __fadd_rn(__fmul_rn(gx, px), __fmul_rn(gy, py));
}
__device__ __forceinline__ float dist2_ref(float g2, float m, float p2) {
    return __fadd_rn(__fsub_rn(g2, __fmul_rn(2.0f, m)), p2);
}
__device__ __forceinline__ int cell_of(float px, float py) {
    int cx = (int)(px * NC); cx = min(max(cx, 0), NC-1);
    int cy = (int)(py * NC); cy = min(max(cy, 0), NC-1);
    return cy * NC + cx;
}
// monotone float -> uint mapping (handles tiny negative fp dist2)
__device__ __forceinline__ unsigned int fkey(float d) {
    unsigned int u = __float_as_uint(d);
    return (u & 0x80000000u) ? ~u : (u | 0x80000000u);
}

// ---- packed fp32x2 (FFMA2) helpers: two independent IEEE fp32 fmas ----
__device__ __forceinline__ ull pack2(float x, float y) {
    ull r; asm("mov.b64 %0, {%1,%2};" : "=l"(r) : "f"(x), "f"(y)); return r;
}
__device__ __forceinline__ ull fma2(ull a, ull b, ull c) {
    ull d; asm("fma.rn.f32x2 %0, %1, %2, %3;" : "=l"(d) : "l"(a), "l"(b), "l"(c)); return d;
}
__device__ __forceinline__ float2 unpack2(ull v) {
    float2 f; asm("mov.b64 {%0,%1}, %2;" : "=f"(f.x), "=f"(f.y) : "l"(v)); return f;
}

// warp bitonic full sort, ascending across lanes (15 stages)
__device__ __forceinline__ ull wsort32(ull key, int lane) {
#pragma unroll
    for (int k = 2; k <= 32; k <<= 1) {
#pragma unroll
        for (int j = k >> 1; j > 0; j >>= 1) {
            ull p = __shfl_xor_sync(FULLMASK, key, j);
            bool up      = ((lane & k) == 0);
            bool keepMin = (((lane & j) == 0) == up);
            ull lo = key < p ? key : p;
            ull hi = key < p ? p : key;
            key = keepMin ? lo : hi;
        }
    }
    return key;
}
// clean a 32-length bitonic sequence into ascending order (5 stages)
__device__ __forceinline__ ull wmerge32(ull key, int lane) {
#pragma unroll
    for (int j = 16; j > 0; j >>= 1) {
        ull p = __shfl_xor_sync(FULLMASK, key, j);
        ull lo = key < p ? key : p;
        ull hi = key < p ? p : key;
        key = ((lane & j) == 0) ? lo : hi;
    }
    return key;
}

// ======================================================================
// Kernel 1: pf = feat @ W_feat^T + b_feat   [20000 x 256]   [R5/R8-proven]
// (hidden under the bin->knn branch; unchanged)
// ======================================================================
__global__ __launch_bounds__(256) void pf_kernel(
    const float* __restrict__ feat,   // [NPTS,64]
    const float* __restrict__ Wf,     // [256,64]
    const float* __restrict__ bf)     // [256]
{
    __shared__ __align__(16) float sW[32*260];   // [kk][c]
    __shared__ __align__(16) float sF[32*36];    // [kk][r]
    const int t    = threadIdx.x;
    const int row0 = blockIdx.x * 32;
    const int ty   = t >> 6;
    const int tx   = t & 63;
    const int r0   = ty * 8;
    const int c0   = tx * 4;

    const float4* feat4 = (const float4*)feat;
    const float4* Wf4   = (const float4*)Wf;

    float4 acc[8];
#pragma unroll
    for (int r = 0; r < 8; r++) acc[r] = make_float4(0.f,0.f,0.f,0.f);

    for (int kt = 0; kt < PD; kt += 32) {
#pragma unroll
        for (int i = 0; i < 8; i++) {
            int lin = i * 256 + t;
            int kk4 = lin & 7;
            int c   = lin >> 3;
            float4 v = Wf4[c*16 + (kt>>2) + kk4];
            sW[(kk4*4+0)*260 + c] = v.x;
            sW[(kk4*4+1)*260 + c] = v.y;
            sW[(kk4*4+2)*260 + c] = v.z;
            sW[(kk4*4+3)*260 + c] = v.w;
        }
        {
            int kk4 = t & 7;
            int r   = t >> 3;
            float4 v = feat4[(size_t)(row0 + r)*16 + (kt>>2) + kk4];
            sF[(kk4*4+0)*36 + r] = v.x;
            sF[(kk4*4+1)*36 + r] = v.y;
            sF[(kk4*4+2)*36 + r] = v.z;
            sF[(kk4*4+3)*36 + r] = v.w;
        }
        __syncthreads();
#pragma unroll
        for (int kk = 0; kk < 32; kk++) {
            float4 w  = *(const float4*)&sW[kk*260 + c0];
            float4 fA = *(const float4*)&sF[kk*36 + r0];
            float4 fB = *(const float4*)&sF[kk*36 + r0 + 4];
            acc[0].x = fmaf(fA.x, w.x, acc[0].x); acc[0].y = fmaf(fA.x, w.y, acc[0].y);
            acc[0].z = fmaf(fA.x, w.z, acc[0].z); acc[0].w = fmaf(fA.x, w.w, acc[0].w);
            acc[1].x = fmaf(fA.y, w.x, acc[1].x); acc[1].y = fmaf(fA.y, w.y, acc[1].y);
            acc[1].z = fmaf(fA.y, w.z, acc[1].z); acc[1].w = fmaf(fA.y, w.w, acc[1].w);
            acc[2].x = fmaf(fA.z, w.x, acc[2].x); acc[2].y = fmaf(fA.z, w.y, acc[2].y);
            acc[2].z = fmaf(fA.z, w.z, acc[2].z); acc[2].w = fmaf(fA.z, w.w, acc[2].w);
            acc[3].x = fmaf(fA.w, w.x, acc[3].x); acc[3].y = fmaf(fA.w, w.y, acc[3].y);
            acc[3].z = fmaf(fA.w, w.z, acc[3].z); acc[3].w = fmaf(fA.w, w.w, acc[3].w);
            acc[4].x = fmaf(fB.x, w.x, acc[4].x); acc[4].y = fmaf(fB.x, w.y, acc[4].y);
            acc[4].z = fmaf(fB.x, w.z, acc[4].z); acc[4].w = fmaf(fB.x, w.w, acc[4].w);
            acc[5].x = fmaf(fB.y, w.x, acc[5].x); acc[5].y = fmaf(fB.y, w.y, acc[5].y);
            acc[5].z = fmaf(fB.y, w.z, acc[5].z); acc[5].w = fmaf(fB.y, w.w, acc[5].w);
            acc[6].x = fmaf(fB.z, w.x, acc[6].x); acc[6].y = fmaf(fB.z, w.y, acc[6].y);
            acc[6].z = fmaf(fB.z, w.z, acc[6].z); acc[6].w = fmaf(fB.z, w.w, acc[6].w);
            acc[7].x = fmaf(fB.w, w.x, acc[7].x); acc[7].y = fmaf(fB.w, w.y, acc[7].y);
            acc[7].z = fmaf(fB.w, w.z, acc[7].z); acc[7].w = fmaf(fB.w, w.w, acc[7].w);
        }
        __syncthreads();
    }
    float4 b4 = *(const float4*)&bf[c0];
    float4* out4 = (float4*)g_pf;
#pragma unroll
    for (int r = 0; r < 8; r++) {
        float4 v = acc[r];
        v.x += b4.x; v.y += b4.y; v.z += b4.z; v.w += b4.w;
        out4[(size_t)(row0 + r0 + r)*64 + tx] = v;
    }
}

// ======================================================================
// Fused binning: count -> scan -> scatter, ONE block, smem counters.
// ======================================================================
__global__ __launch_bounds__(1024) void bin_all_kernel(const float* __restrict__ pc)
{
    __shared__ int scnt[NCELLS];   // 16 KB
    __shared__ int wsum[32];
    const int t = threadIdx.x;
    const float2* __restrict__ pc2 = (const float2*)pc;

    for (int i = t; i < NCELLS; i += 1024) scnt[i] = 0;
    __syncthreads();

    for (int n = t; n < NPTS; n += 1024) {
        float2 p = pc2[n];
        atomicAdd(&scnt[cell_of(p.x, p.y)], 1);
    }
    __syncthreads();

    int v[4], s = 0;
#pragma unroll
    for (int i = 0; i < 4; i++) { v[i] = scnt[t*4 + i]; s += v[i]; }
    const int lane = t & 31, wid = t >> 5;
    int incl = s;
#pragma unroll
    for (int o = 1; o < 32; o <<= 1) {
        int u = __shfl_up_sync(FULLMASK, incl, o);
        if (lane >= o) incl += u;
    }
    if (lane == 31) wsum[wid] = incl;
    __syncthreads();
    if (wid == 0) {
        int ws = wsum[lane];
#pragma unroll
        for (int o = 1; o < 32; o <<= 1) {
            int u = __shfl_up_sync(FULLMASK, ws, o);
            if (lane >= o) ws += u;
        }
        wsum[lane] = ws;
    }
    __syncthreads();
    int run = (wid > 0 ? wsum[wid-1] : 0) + incl - s;
    int starts[4];
#pragma unroll
    for (int i = 0; i < 4; i++) {
        starts[i] = run;
        g_start[t*4 + i] = run;
        run += v[i];
    }
    if (t == 1023) g_start[NCELLS] = run;
    __syncthreads();
#pragma unroll
    for (int i = 0; i < 4; i++) scnt[t*4 + i] = starts[i];
    __syncthreads();

    for (int n = t; n < NPTS; n += 1024) {
        float2 p = pc2[n];
        int pos = atomicAdd(&scnt[cell_of(p.x, p.y)], 1);
        g_pts[pos] = make_float4(p.x, p.y, sum_sq(p.x, p.y), __int_as_float(n));
    }
}

// ======================================================================
// Kernel: exact KNN (K=32), WARP PER GRID POINT, register top-32. [R9]
// ======================================================================
__global__ __launch_bounds__(256) void knn_kernel()
{
    const int t    = threadIdx.x;
    const int lane = t & 31;
    const int g    = blockIdx.x * GPB + (t >> 5);

    const int wx = g % WW, hy = g / WW;
    const float gx = grid_coord(wx), gy = grid_coord(hy);
    const float g2 = sum_sq(gx, gy);

    float R2 = 8.0e-4f;
    if (gx < 0.03f || gx > 0.97f) R2 *= 2.0f;
    if (gy < 0.03f || gy > 0.97f) R2 *= 2.0f;

    ull top = SENT;
    for (int iter = 0; iter < 16; iter++) {
        top = SENT;
        float R = sqrtf(R2);
        int cx0 = max(0,    (int)floorf((gx - R) * NC));
        int cx1 = min(NC-1, (int)floorf((gx + R) * NC));
        int cy0 = max(0,    (int)floorf((gy - R) * NC));
        int cy1 = min(NC-1, (int)floorf((gy + R) * NC));

        for (int cy = cy0; cy <= cy1; cy++) {
            int b = __ldg(&g_start[cy*NC + cx0]);
            int e = __ldg(&g_start[cy*NC + cx1 + 1]);
            for (int base = b; base < e; base += 32) {
                int j = base + lane;
                ull key = SENT;
                if (j < e) {
                    float4 p = g_pts[j];
                    float m = dot_ref(gx, gy, p.x, p.y);
                    float d = dist2_ref(g2, m, p.z);
                    key = ((ull)fkey(d) << 32) | (unsigned int)__float_as_int(p.w);
                }
                ull worst = __shfl_sync(FULLMASK, top, 31);
                if (__any_sync(FULLMASK, key < worst)) {
                    key = wsort32(key, lane);                            // asc
                    ull rev = __shfl_sync(FULLMASK, key, 31 - lane);
                    ull mk  = top < rev ? top : rev;                     // bitonic
                    top = wmerge32(mk, lane);                            // asc
                }
            }
        }
        ull worst = __shfl_sync(FULLMASK, top, 31);
        if ((unsigned int)(worst >> 32) <= fkey(R2)) break;
        R2 *= 2.0f;
    }
    g_knn[g*KNN + lane] = (int)(unsigned int)(top & 0xffffffffull);
}

// ======================================================================
// Kernel: attention MLP + softmax + weighted gather.  [R7/R8-proven]
// ======================================================================
__global__ __launch_bounds__(256) void attn_gather_kernel(
    const float* __restrict__ pc,
    const float* __restrict__ W1, const float* __restrict__ b1,
    const float* __restrict__ W2, const float* __restrict__ b2)
{
    __shared__ __align__(16) float4 sW14[HID];   // (w0,w1,w2,b1)
    __shared__ float  sW2[HID];
    __shared__ float  swt[GPB][KNN];
    __shared__ int    soff[GPB][KNN];            // float4 row offsets

    const int t = threadIdx.x;
    const int w = t >> 5;
    const int l = t & 31;
    const int g = blockIdx.x * GPB + w;

    if (t < HID) {
        sW14[t] = make_float4(W1[t*3], W1[t*3+1], W1[t*3+2], b1[t]);
        sW2[t]  = W2[t];
    }

    const int wx = g % WW, hy = g / WW;
    const float gx = grid_coord(wx), gy = grid_coord(hy);

    const int id = g_knn[g*KNN + l];
    const float px = pc[2*id], py = pc[2*id+1];
    const float dx = __fsub_rn(gx, px), dy = __fsub_rn(gy, py);
    const float dd = sqrtf(sum_sq(dx, dy));
    __syncthreads();

    float acc = 0.0f;
#pragma unroll 16
    for (int j = 0; j < HID; j++) {
        float4 wv = sW14[j];
        float pre = fmaf(wv.x, dx, fmaf(wv.y, dy, fmaf(wv.z, dd, wv.w)));
        float ge  = 0.5f * pre * (1.0f + erff(pre * 0.70710678118654752f));
        acc = fmaf(sW2[j], ge, acc);
    }
    float logit = acc + b2[0];

    float m = logit;
#pragma unroll
    for (int o = 16; o >= 1; o >>= 1) m = fmaxf(m, __shfl_xor_sync(FULLMASK, m, o));
    float e = expf(logit - m);
    float s = e;
#pragma unroll
    for (int o = 16; o >= 1; o >>= 1) s += __shfl_xor_sync(FULLMASK, s, o);
    swt[w][l]  = e / s;
    soff[w][l] = id * (GD/4);
    __syncwarp();

    const float4* __restrict__ pf4 = (const float4*)g_pf;
    float4 a0 = make_float4(0.f,0.f,0.f,0.f);
    float4 a1 = make_float4(0.f,0.f,0.f,0.f);
#pragma unroll 8
    for (int k = 0; k < KNN; k++) {
        float wk = swt[w][k];
        int   ro = soff[w][k];
        float4 v0 = pf4[(size_t)ro + l];
        float4 v1 = pf4[(size_t)ro + 32 + l];
        a0.x = fmaf(wk, v0.x, a0.x); a0.y = fmaf(wk, v0.y, a0.y);
        a0.z = fmaf(wk, v0.z, a0.z); a0.w = fmaf(wk, v0.w, a0.w);
        a1.x = fmaf(wk, v1.x, a1.x); a1.y = fmaf(wk, v1.y, a1.y);
        a1.z = fmaf(wk, v1.z, a1.z); a1.w = fmaf(wk, v1.w, a1.w);
    }
    float4* mid4 = (float4*)g_mid;
    mid4[(size_t)g*(GD/4) + l]      = a0;
    mid4[(size_t)g*(GD/4) + 32 + l] = a1;
}

// ======================================================================
// Kernel: out = mid @ W_out^T + b_out, then LayerNorm.
// NEW: packed fp32x2 FFMA2 inner loop (2 fp32 FMA per issue slot).
// Rows are paired (natural smem adjacency -> LDS.64); w duplicated into
// packed pairs. Per-element accumulation order unchanged (kk-ascending,
// IEEE fma) -> bit-identical results.
// ======================================================================
__global__ __launch_bounds__(256) void outproj_ln_kernel(
    const float* __restrict__ Wo,   // [256,256]
    const float* __restrict__ bo,
    const float* __restrict__ lng,
    const float* __restrict__ lnb,
    float* __restrict__ out)
{
    __shared__ __align__(16) float sW[32*260];   // [kk][c]; reused as sOut [r][c]
    __shared__ __align__(16) float sF[32*36];    // [kk][r]
    __shared__ float sMu[32], sRs[32];

    const int t    = threadIdx.x;
    const int row0 = blockIdx.x * 32;
    const int ty   = t >> 6;
    const int tx   = t & 63;
    const int r0   = ty * 8;
    const int c0   = tx * 4;

    const float4* Wo4  = (const float4*)Wo;
    const float4* mid4 = (const float4*)g_mid;

    // accp[c][rp] = packed (acc[2rp][c], acc[2rp+1][c])
    ull accp[4][4];
#pragma unroll
    for (int c = 0; c < 4; c++)
#pragma unroll
        for (int rp = 0; rp < 4; rp++) accp[c][rp] = 0ull;

    for (int kt = 0; kt < GD; kt += 32) {
#pragma unroll
        for (int i = 0; i < 8; i++) {
            int lin = i * 256 + t;
            int kk4 = lin & 7;
            int c   = lin >> 3;
            float4 v = Wo4[c*64 + (kt>>2) + kk4];
            sW[(kk4*4+0)*260 + c] = v.x;
            sW[(kk4*4+1)*260 + c] = v.y;
            sW[(kk4*4+2)*260 + c] = v.z;
            sW[(kk4*4+3)*260 + c] = v.w;
        }
        {
            int kk4 = t & 7;
            int r   = t >> 3;
            float4 v = mid4[(size_t)(row0 + r)*64 + (kt>>2) + kk4];
            sF[(kk4*4+0)*36 + r] = v.x;
            sF[(kk4*4+1)*36 + r] = v.y;
            sF[(kk4*4+2)*36 + r] = v.z;
            sF[(kk4*4+3)*36 + r] = v.w;
        }
        __syncthreads();
#pragma unroll
        for (int kk = 0; kk < 32; kk++) {
            float4 w = *(const float4*)&sW[kk*260 + c0];
            ull wx = pack2(w.x, w.x);
            ull wy = pack2(w.y, w.y);
            ull wz = pack2(w.z, w.z);
            ull ww = pack2(w.w, w.w);
            const ull* aU = (const ull*)&sF[kk*36 + r0];   // 8-byte aligned
            ull a01 = aU[0], a23 = aU[1], a45 = aU[2], a67 = aU[3];
            accp[0][0] = fma2(a01, wx, accp[0][0]);
            accp[0][1] = fma2(a23, wx, accp[0][1]);
            accp[0][2] = fma2(a45, wx, accp[0][2]);
            accp[0][3] = fma2(a67, wx, accp[0][3]);
            accp[1][0] = fma2(a01, wy, accp[1][0]);
            accp[1][1] = fma2(a23, wy, accp[1][1]);
            accp[1][2] = fma2(a45, wy, accp[1][2]);
            accp[1][3] = fma2(a67, wy, accp[1][3]);
            accp[2][0] = fma2(a01, wz, accp[2][0]);
            accp[2][1] = fma2(a23, wz, accp[2][1]);
            accp[2][2] = fma2(a45, wz, accp[2][2]);
            accp[2][3] = fma2(a67, wz, accp[2][3]);
            accp[3][0] = fma2(a01, ww, accp[3][0]);
            accp[3][1] = fma2(a23, ww, accp[3][1]);
            accp[3][2] = fma2(a45, ww, accp[3][2]);
            accp[3][3] = fma2(a67, ww, accp[3][3]);
        }
        __syncthreads();
    }

    // unpack, add bias, stage rows into sW reused as sOut [r][260]
    float4 b4 = *(const float4*)&bo[c0];
#pragma unroll
    for (int rp = 0; rp < 4; rp++) {
        float2 p0 = unpack2(accp[0][rp]);
        float2 p1 = unpack2(accp[1][rp]);
        float2 p2 = unpack2(accp[2][rp]);
        float2 p3 = unpack2(accp[3][rp]);
        int ra = r0 + 2*rp;
        float4 va = make_float4(p0.x + b4.x, p1.x + b4.y, p2.x + b4.z, p3.x + b4.w);
        float4 vb = make_float4(p0.y + b4.x, p1.y + b4.y, p2.y + b4.z, p3.y + b4.w);
        *(float4*)&sW[ra*260 + c0]     = va;
        *(float4*)&sW[(ra+1)*260 + c0] = vb;
    }
    __syncthreads();

    const int lane = t & 31, wid = t >> 5;
    for (int r = wid; r < 32; r += 8) {
        float s = 0.0f;
#pragma unroll
        for (int i = lane; i < GD; i += 32) s += sW[r*260 + i];
#pragma unroll
        for (int o = 16; o >= 1; o >>= 1) s += __shfl_xor_sync(FULLMASK, s, o);
        float mu = s * (1.0f / GD);
        float v = 0.0f;
#pragma unroll
        for (int i = lane; i < GD; i += 32) {
            float d = sW[r*260 + i] - mu;
            v = fmaf(d, d, v);
        }
#pragma unroll
        for (int o = 16; o >= 1; o >>= 1) v += __shfl_xor_sync(FULLMASK, v, o);
        if (lane == 0) { sMu[r] = mu; sRs[r] = rsqrtf(v * (1.0f / GD) + EPSLN); }
    }
    __syncthreads();

    float4 g4 = *(const float4*)&lng[c0];
    float4 be4 = *(const float4*)&lnb[c0];
    float4* out4 = (float4*)out;
#pragma unroll
    for (int r = 0; r < 8; r++) {
        int rr = r0 + r;
        float mu = sMu[rr], rs = sRs[rr];
        float4 v = *(const float4*)&sW[rr*260 + c0];
        v.x = (v.x - mu) * rs * g4.x + be4.x;
        v.y = (v.y - mu) * rs * g4.y + be4.y;
        v.z = (v.z - mu) * rs * g4.z + be4.z;
        v.w = (v.w - mu) * rs * g4.w + be4.w;
        out4[(size_t)(row0 + rr)*64 + tx] = v;
    }
}

// ======================================================================
// launcher — fork/join: pf runs concurrently with bin->knn.
// ======================================================================
extern "C" void kernel_launch(void* const* d_in, const int* in_sizes, int n_in,
                              void* d_out, int out_size)
{
    const float* point_features = (const float*)d_in[0];
    const float* point_coords   = (const float*)d_in[1];
    const float* W_feat         = (const float*)d_in[2];
    const float* b_feat         = (const float*)d_in[3];
    const float* W1             = (const float*)d_in[4];
    const float* b1             = (const float*)d_in[5];
    const float* W2             = (const float*)d_in[6];
    const float* b2             = (const float*)d_in[7];
    const float* W_out          = (const float*)d_in[8];
    const float* b_out          = (const float*)d_in[9];
    const float* ln_g           = (const float*)d_in[10];
    const float* ln_b           = (const float*)d_in[11];
    float* out = (float*)d_out;

    cudaStream_t s1;
    cudaStreamCreateWithFlags(&s1, cudaStreamNonBlocking);
    cudaEvent_t evFork, evJoin;
    cudaEventCreateWithFlags(&evFork, cudaEventDisableTiming);
    cudaEventCreateWithFlags(&evJoin, cudaEventDisableTiming);

    // fork: branch A (pf) on s1
    cudaEventRecord(evFork, 0);
    cudaStreamWaitEvent(s1, evFork, 0);
    pf_kernel<<<NPTS/32, 256, 0, s1>>>(point_features, W_feat, b_feat);
    cudaEventRecord(evJoin, s1);

    // branch B (bin -> knn) on the main (capture) stream
    bin_all_kernel<<<1, 1024>>>(point_coords);
    knn_kernel<<<G/GPB, 256>>>();

    // join: attn needs both pf and knn
    cudaStreamWaitEvent(0, evJoin, 0);
    attn_gather_kernel<<<G/GPB, 256>>>(point_coords, W1, b1, W2, b2);
    outproj_ln_kernel<<<G/32, 256>>>(W_out, b_out, ln_g, ln_b, out);

    cudaEventDestroy(evFork);
    cudaEventDestroy(evJoin);
    cudaStreamDestroy(s1);
}

// round 12
// speedup vs baseline: 1.7567x; 1.0422x over previous
#include <cuda_runtime.h>
#include <cuda_bf16.h>
#include <math.h>
#include <float.h>

// ---------------- problem constants (fixed dataset) ----------------
#define NPTS    20000
#define PD      64          // point feature dim
#define GD      256         // grid feature dim
#define HH      96
#define WW      96
#define G       (HH*WW)     // 9216 grid points
#define KNN     32
#define HID     64
#define NC      64          // bin grid 64x64
#define NCELLS  (NC*NC)
#define EPSLN   1e-5f
#define GPB     8           // grid points per attn/knn block (8 warps)

// step = f32(1/95), exactly as JAX f32 linspace computes it
#define STEP    (1.0f/95.0f)

#define FULLMASK 0xffffffffu
#define SENT     0xffffffffffffffffull

typedef unsigned long long ull;

// ---------------- scratch (device globals, no allocations) ----------------
__device__ float  g_pf[NPTS*GD];       // projected point features (20.5 MB)
__device__ int    g_start[NCELLS+1];
__device__ float4 g_pts[NPTS];         // (px, py, p2, idx-as-float), binned order
__device__ int    g_knn[G*KNN];
__device__ float  g_mid[G*GD];         // aggregated features before out-proj

// exact-rounding helpers for the KNN distance path (must bit-match reference)
__device__ __forceinline__ float grid_coord(int i) {
    return __fmul_rn((float)i, STEP);
}
__device__ __forceinline__ float sum_sq(float x, float y) {
    return __fadd_rn(__fmul_rn(x, x), __fmul_rn(y, y));
}
__device__ __forceinline__ float dot_ref(float gx, float gy, float px, float py) {
    return __fadd_rn(__fmul_rn(gx, px), __fmul_rn(gy, py));
}
__device__ __forceinline__ float dist2_ref(float g2, float m, float p2) {
    return __fadd_rn(__fsub_rn(g2, __fmul_rn(2.0f, m)), p2);
}
__device__ __forceinline__ int cell_of(float px, float py) {
    int cx = (int)(px * NC); cx = min(max(cx, 0), NC-1);
    int cy = (int)(py * NC); cy = min(max(cy, 0), NC-1);
    return cy * NC + cx;
}
// monotone float -> uint mapping (handles tiny negative fp dist2)
__device__ __forceinline__ unsigned int fkey(float d) {
    unsigned int u = __float_as_uint(d);
    return (u & 0x80000000u) ? ~u : (u | 0x80000000u);
}

// ---- packed fp32x2 (FFMA2) helpers ----
__device__ __forceinline__ ull pack2(float x, float y) {
    ull r; asm("mov.b64 %0, {%1,%2};" : "=l"(r) : "f"(x), "f"(y)); return r;
}
__device__ __forceinline__ ull fma2(ull a, ull b, ull c) {
    ull d; asm("fma.rn.f32x2 %0, %1, %2, %3;" : "=l"(d) : "l"(a), "l"(b), "l"(c)); return d;
}
__device__ __forceinline__ float2 unpack2(ull v) {
    float2 f; asm("mov.b64 {%0,%1}, %2;" : "=f"(f.x), "=f"(f.y) : "l"(v)); return f;
}

// warp bitonic full sort, ascending across lanes (15 stages)
__device__ __forceinline__ ull wsort32(ull key, int lane) {
#pragma unroll
    for (int k = 2; k <= 32; k <<= 1) {
#pragma unroll
        for (int j = k >> 1; j > 0; j >>= 1) {
            ull p = __shfl_xor_sync(FULLMASK, key, j);
            bool up      = ((lane & k) == 0);
            bool keepMin = (((lane & j) == 0) == up);
            ull lo = key < p ? key : p;
            ull hi = key < p ? p : key;
            key = keepMin ? lo : hi;
        }
    }
    return key;
}
// clean a 32-length bitonic sequence into ascending order (5 stages)
__device__ __forceinline__ ull wmerge32(ull key, int lane) {
#pragma unroll
    for (int j = 16; j > 0; j >>= 1) {
        ull p = __shfl_xor_sync(FULLMASK, key, j);
        ull lo = key < p ? key : p;
        ull hi = key < p ? p : key;
        key = ((lane & j) == 0) ? lo : hi;
    }
    return key;
}

// ======================================================================
// Kernel 1: pf = feat @ W_feat^T + b_feat   [20000 x 256]   [R5/R8-proven]
// ======================================================================
__global__ __launch_bounds__(256) void pf_kernel(
    const float* __restrict__ feat,   // [NPTS,64]
    const float* __restrict__ Wf,     // [256,64]
    const float* __restrict__ bf)     // [256]
{
    __shared__ __align__(16) float sW[32*260];   // [kk][c]
    __shared__ __align__(16) float sF[32*36];    // [kk][r]
    const int t    = threadIdx.x;
    const int row0 = blockIdx.x * 32;
    const int ty   = t >> 6;
    const int tx   = t & 63;
    const int r0   = ty * 8;
    const int c0   = tx * 4;

    const float4* feat4 = (const float4*)feat;
    const float4* Wf4   = (const float4*)Wf;

    float4 acc[8];
#pragma unroll
    for (int r = 0; r < 8; r++) acc[r] = make_float4(0.f,0.f,0.f,0.f);

    for (int kt = 0; kt < PD; kt += 32) {
#pragma unroll
        for (int i = 0; i < 8; i++) {
            int lin = i * 256 + t;
            int kk4 = lin & 7;
            int c   = lin >> 3;
            float4 v = Wf4[c*16 + (kt>>2) + kk4];
            sW[(kk4*4+0)*260 + c] = v.x;
            sW[(kk4*4+1)*260 + c] = v.y;
            sW[(kk4*4+2)*260 + c] = v.z;
            sW[(kk4*4+3)*260 + c] = v.w;
        }
        {
            int kk4 = t & 7;
            int r   = t >> 3;
            float4 v = feat4[(size_t)(row0 + r)*16 + (kt>>2) + kk4];
            sF[(kk4*4+0)*36 + r] = v.x;
            sF[(kk4*4+1)*36 + r] = v.y;
            sF[(kk4*4+2)*36 + r] = v.z;
            sF[(kk4*4+3)*36 + r] = v.w;
        }
        __syncthreads();
#pragma unroll
        for (int kk = 0; kk < 32; kk++) {
            float4 w  = *(const float4*)&sW[kk*260 + c0];
            float4 fA = *(const float4*)&sF[kk*36 + r0];
            float4 fB = *(const float4*)&sF[kk*36 + r0 + 4];
            acc[0].x = fmaf(fA.x, w.x, acc[0].x); acc[0].y = fmaf(fA.x, w.y, acc[0].y);
            acc[0].z = fmaf(fA.x, w.z, acc[0].z); acc[0].w = fmaf(fA.x, w.w, acc[0].w);
            acc[1].x = fmaf(fA.y, w.x, acc[1].x); acc[1].y = fmaf(fA.y, w.y, acc[1].y);
            acc[1].z = fmaf(fA.y, w.z, acc[1].z); acc[1].w = fmaf(fA.y, w.w, acc[1].w);
            acc[2].x = fmaf(fA.z, w.x, acc[2].x); acc[2].y = fmaf(fA.z, w.y, acc[2].y);
            acc[2].z = fmaf(fA.z, w.z, acc[2].z); acc[2].w = fmaf(fA.z, w.w, acc[2].w);
            acc[3].x = fmaf(fA.w, w.x, acc[3].x); acc[3].y = fmaf(fA.w, w.y, acc[3].y);
            acc[3].z = fmaf(fA.w, w.z, acc[3].z); acc[3].w = fmaf(fA.w, w.w, acc[3].w);
            acc[4].x = fmaf(fB.x, w.x, acc[4].x); acc[4].y = fmaf(fB.x, w.y, acc[4].y);
            acc[4].z = fmaf(fB.x, w.z, acc[4].z); acc[4].w = fmaf(fB.x, w.w, acc[4].w);
            acc[5].x = fmaf(fB.y, w.x, acc[5].x); acc[5].y = fmaf(fB.y, w.y, acc[5].y);
            acc[5].z = fmaf(fB.y, w.z, acc[5].z); acc[5].w = fmaf(fB.y, w.w, acc[5].w);
            acc[6].x = fmaf(fB.z, w.x, acc[6].x); acc[6].y = fmaf(fB.z, w.y, acc[6].y);
            acc[6].z = fmaf(fB.z, w.z, acc[6].z); acc[6].w = fmaf(fB.z, w.w, acc[6].w);
            acc[7].x = fmaf(fB.w, w.x, acc[7].x); acc[7].y = fmaf(fB.w, w.y, acc[7].y);
            acc[7].z = fmaf(fB.w, w.z, acc[7].z); acc[7].w = fmaf(fB.w, w.w, acc[7].w);
        }
        __syncthreads();
    }
    float4 b4 = *(const float4*)&bf[c0];
    float4* out4 = (float4*)g_pf;
#pragma unroll
    for (int r = 0; r < 8; r++) {
        float4 v = acc[r];
        v.x += b4.x; v.y += b4.y; v.z += b4.z; v.w += b4.w;
        out4[(size_t)(row0 + r0 + r)*64 + tx] = v;
    }
}

// ======================================================================
// Fused binning: count -> scan -> scatter, ONE block, smem counters.
// ======================================================================
__global__ __launch_bounds__(1024) void bin_all_kernel(const float* __restrict__ pc)
{
    __shared__ int scnt[NCELLS];   // 16 KB
    __shared__ int wsum[32];
    const int t = threadIdx.x;
    const float2* __restrict__ pc2 = (const float2*)pc;

    for (int i = t; i < NCELLS; i += 1024) scnt[i] = 0;
    __syncthreads();

    for (int n = t; n < NPTS; n += 1024) {
        float2 p = pc2[n];
        atomicAdd(&scnt[cell_of(p.x, p.y)], 1);
    }
    __syncthreads();

    int v[4], s = 0;
#pragma unroll
    for (int i = 0; i < 4; i++) { v[i] = scnt[t*4 + i]; s += v[i]; }
    const int lane = t & 31, wid = t >> 5;
    int incl = s;
#pragma unroll
    for (int o = 1; o < 32; o <<= 1) {
        int u = __shfl_up_sync(FULLMASK, incl, o);
        if (lane >= o) incl += u;
    }
    if (lane == 31) wsum[wid] = incl;
    __syncthreads();
    if (wid == 0) {
        int ws = wsum[lane];
#pragma unroll
        for (int o = 1; o < 32; o <<= 1) {
            int u = __shfl_up_sync(FULLMASK, ws, o);
            if (lane >= o) ws += u;
        }
        wsum[lane] = ws;
    }
    __syncthreads();
    int run = (wid > 0 ? wsum[wid-1] : 0) + incl - s;
    int starts[4];
#pragma unroll
    for (int i = 0; i < 4; i++) {
        starts[i] = run;
        g_start[t*4 + i] = run;
        run += v[i];
    }
    if (t == 1023) g_start[NCELLS] = run;
    __syncthreads();
#pragma unroll
    for (int i = 0; i < 4; i++) scnt[t*4 + i] = starts[i];
    __syncthreads();

    for (int n = t; n < NPTS; n += 1024) {
        float2 p = pc2[n];
        int pos = atomicAdd(&scnt[cell_of(p.x, p.y)], 1);
        g_pts[pos] = make_float4(p.x, p.y, sum_sq(p.x, p.y), __int_as_float(n));
    }
}

// ======================================================================
// Kernel: exact KNN (K=32), WARP PER GRID POINT, register top-32.
// NEW: ballot-compaction pending buffer -> sort+merge only when 32
// survivors (d<=R2) accumulate. ~2 merges instead of ~5.
// Exactness: retry doubles R2 until worst(32nd) <= R2; out-of-box
// points have d > R^2 >= worst, filtered points have d > R2 >= worst.
// ======================================================================
__global__ __launch_bounds__(256) void knn_kernel()
{
    __shared__ ull sb[GPB][KNN];   // per-warp pending buffer (2 KB)

    const int t    = threadIdx.x;
    const int lane = t & 31;
    const int w    = t >> 5;
    const int g    = blockIdx.x * GPB + w;

    const int wx = g % WW, hy = g / WW;
    const float gx = grid_coord(wx), gy = grid_coord(hy);
    const float g2 = sum_sq(gx, gy);

    float R2 = 8.0e-4f;
    if (gx < 0.03f || gx > 0.97f) R2 *= 2.0f;
    if (gy < 0.03f || gy > 0.97f) R2 *= 2.0f;

    ull top = SENT;
    for (int iter = 0; iter < 16; iter++) {
        top = SENT;
        int pcnt = 0;
        const float R = sqrtf(R2);
        const unsigned int kR2 = fkey(R2);
        int cx0 = max(0,    (int)floorf((gx - R) * NC));
        int cx1 = min(NC-1, (int)floorf((gx + R) * NC));
        int cy0 = max(0,    (int)floorf((gy - R) * NC));
        int cy1 = min(NC-1, (int)floorf((gy + R) * NC));

        for (int cy = cy0; cy <= cy1; cy++) {
            int b = __ldg(&g_start[cy*NC + cx0]);
            int e = __ldg(&g_start[cy*NC + cx1 + 1]);
            for (int base = b; base < e; base += 32) {
                int j = base + lane;
                ull key = SENT;
                bool valid = false;
                if (j < e) {
                    float4 p = g_pts[j];
                    float m = dot_ref(gx, gy, p.x, p.y);
                    float d = dist2_ref(g2, m, p.z);
                    unsigned int kd = fkey(d);
                    if (kd <= kR2) {
                        valid = true;
                        key = ((ull)kd << 32) | (unsigned int)__float_as_int(p.w);
                    }
                }
                unsigned mask = __ballot_sync(FULLMASK, valid);
                int c = __popc(mask);
                if (c == 0) continue;
                int r   = __popc(mask & ((1u << lane) - 1u));
                int pos = pcnt + r;
                if (valid && pos < KNN) sb[w][pos] = key;
                pcnt += c;
                if (pcnt >= KNN) {
                    __syncwarp();
                    ull pend = sb[w][lane];
                    ull sk  = wsort32(pend, lane);
                    ull rev = __shfl_sync(FULLMASK, sk, 31 - lane);
                    ull mk  = top < rev ? top : rev;
                    top = wmerge32(mk, lane);
                    pcnt -= KNN;
                    __syncwarp();
                    if (valid && pos >= KNN) sb[w][pos - KNN] = key;
                    __syncwarp();
                }
            }
        }
        if (pcnt > 0) {
            __syncwarp();
            ull pend = (lane < pcnt) ? sb[w][lane] : SENT;
            ull sk  = wsort32(pend, lane);
            ull rev = __shfl_sync(FULLMASK, sk, 31 - lane);
            ull mk  = top < rev ? top : rev;
            top = wmerge32(mk, lane);
        }
        ull worst = __shfl_sync(FULLMASK, top, 31);
        if ((unsigned int)(worst >> 32) <= kR2) break;
        R2 *= 2.0f;
    }
    g_knn[g*KNN + lane] = (int)(unsigned int)(top & 0xffffffffull);
}

// ======================================================================
// Kernel: attention MLP + softmax + weighted gather.  [R7/R8-proven]
// ======================================================================
__global__ __launch_bounds__(256) void attn_gather_kernel(
    const float* __restrict__ pc,
    const float* __restrict__ W1, const float* __restrict__ b1,
    const float* __restrict__ W2, const float* __restrict__ b2)
{
    __shared__ __align__(16) float4 sW14[HID];   // (w0,w1,w2,b1)
    __shared__ float  sW2[HID];
    __shared__ float  swt[GPB][KNN];
    __shared__ int    soff[GPB][KNN];            // float4 row offsets

    const int t = threadIdx.x;
    const int w = t >> 5;
    const int l = t & 31;
    const int g = blockIdx.x * GPB + w;

    if (t < HID) {
        sW14[t] = make_float4(W1[t*3], W1[t*3+1], W1[t*3+2], b1[t]);
        sW2[t]  = W2[t];
    }

    const int wx = g % WW, hy = g / WW;
    const float gx = grid_coord(wx), gy = grid_coord(hy);

    const int id = g_knn[g*KNN + l];
    const float px = pc[2*id], py = pc[2*id+1];
    const float dx = __fsub_rn(gx, px), dy = __fsub_rn(gy, py);
    const float dd = sqrtf(sum_sq(dx, dy));
    __syncthreads();

    float acc = 0.0f;
#pragma unroll 16
    for (int j = 0; j < HID; j++) {
        float4 wv = sW14[j];
        float pre = fmaf(wv.x, dx, fmaf(wv.y, dy, fmaf(wv.z, dd, wv.w)));
        float ge  = 0.5f * pre * (1.0f + erff(pre * 0.70710678118654752f));
        acc = fmaf(sW2[j], ge, acc);
    }
    float logit = acc + b2[0];

    float m = logit;
#pragma unroll
    for (int o = 16; o >= 1; o >>= 1) m = fmaxf(m, __shfl_xor_sync(FULLMASK, m, o));
    float e = expf(logit - m);
    float s = e;
#pragma unroll
    for (int o = 16; o >= 1; o >>= 1) s += __shfl_xor_sync(FULLMASK, s, o);
    swt[w][l]  = e / s;
    soff[w][l] = id * (GD/4);
    __syncwarp();

    const float4* __restrict__ pf4 = (const float4*)g_pf;
    float4 a0 = make_float4(0.f,0.f,0.f,0.f);
    float4 a1 = make_float4(0.f,0.f,0.f,0.f);
#pragma unroll 8
    for (int k = 0; k < KNN; k++) {
        float wk = swt[w][k];
        int   ro = soff[w][k];
        float4 v0 = pf4[(size_t)ro + l];
        float4 v1 = pf4[(size_t)ro + 32 + l];
        a0.x = fmaf(wk, v0.x, a0.x); a0.y = fmaf(wk, v0.y, a0.y);
        a0.z = fmaf(wk, v0.z, a0.z); a0.w = fmaf(wk, v0.w, a0.w);
        a1.x = fmaf(wk, v1.x, a1.x); a1.y = fmaf(wk, v1.y, a1.y);
        a1.z = fmaf(wk, v1.z, a1.z); a1.w = fmaf(wk, v1.w, a1.w);
    }
    float4* mid4 = (float4*)g_mid;
    mid4[(size_t)g*(GD/4) + l]      = a0;
    mid4[(size_t)g*(GD/4) + 32 + l] = a1;
}

// ======================================================================
// Kernel: out = mid @ W_out^T + b_out, then LayerNorm. [R11 FFMA2]
// ======================================================================
__global__ __launch_bounds__(256) void outproj_ln_kernel(
    const float* __restrict__ Wo,   // [256,256]
    const float* __restrict__ bo,
    const float* __restrict__ lng,
    const float* __restrict__ lnb,
    float* __restrict__ out)
{
    __shared__ __align__(16) float sW[32*260];   // [kk][c]; reused as sOut [r][c]
    __shared__ __align__(16) float sF[32*36];    // [kk][r]
    __shared__ float sMu[32], sRs[32];

    const int t    = threadIdx.x;
    const int row0 = blockIdx.x * 32;
    const int ty   = t >> 6;
    const int tx   = t & 63;
    const int r0   = ty * 8;
    const int c0   = tx * 4;

    const float4* Wo4  = (const float4*)Wo;
    const float4* mid4 = (const float4*)g_mid;

    ull accp[4][4];
#pragma unroll
    for (int c = 0; c < 4; c++)
#pragma unroll
        for (int rp = 0; rp < 4; rp++) accp[c][rp] = 0ull;

    for (int kt = 0; kt < GD; kt += 32) {
#pragma unroll
        for (int i = 0; i < 8; i++) {
            int lin = i * 256 + t;
            int kk4 = lin & 7;
            int c   = lin >> 3;
            float4 v = Wo4[c*64 + (kt>>2) + kk4];
            sW[(kk4*4+0)*260 + c] = v.x;
            sW[(kk4*4+1)*260 + c] = v.y;
            sW[(kk4*4+2)*260 + c] = v.z;
            sW[(kk4*4+3)*260 + c] = v.w;
        }
        {
            int kk4 = t & 7;
            int r   = t >> 3;
            float4 v = mid4[(size_t)(row0 + r)*64 + (kt>>2) + kk4];
            sF[(kk4*4+0)*36 + r] = v.x;
            sF[(kk4*4+1)*36 + r] = v.y;
            sF[(kk4*4+2)*36 + r] = v.z;
            sF[(kk4*4+3)*36 + r] = v.w;
        }
        __syncthreads();
#pragma unroll
        for (int kk = 0; kk < 32; kk++) {
            float4 w = *(const float4*)&sW[kk*260 + c0];
            ull wx = pack2(w.x, w.x);
            ull wy = pack2(w.y, w.y);
            ull wz = pack2(w.z, w.z);
            ull ww = pack2(w.w, w.w);
            const ull* aU = (const ull*)&sF[kk*36 + r0];
            ull a01 = aU[0], a23 = aU[1], a45 = aU[2], a67 = aU[3];
            accp[0][0] = fma2(a01, wx, accp[0][0]);
            accp[0][1] = fma2(a23, wx, accp[0][1]);
            accp[0][2] = fma2(a45, wx, accp[0][2]);
            accp[0][3] = fma2(a67, wx, accp[0][3]);
            accp[1][0] = fma2(a01, wy, accp[1][0]);
            accp[1][1] = fma2(a23, wy, accp[1][1]);
            accp[1][2] = fma2(a45, wy, accp[1][2]);
            accp[1][3] = fma2(a67, wy, accp[1][3]);
            accp[2][0] = fma2(a01, wz, accp[2][0]);
            accp[2][1] = fma2(a23, wz, accp[2][1]);
            accp[2][2] = fma2(a45, wz, accp[2][2]);
            accp[2][3] = fma2(a67, wz, accp[2][3]);
            accp[3][0] = fma2(a01, ww, accp[3][0]);
            accp[3][1] = fma2(a23, ww, accp[3][1]);
            accp[3][2] = fma2(a45, ww, accp[3][2]);
            accp[3][3] = fma2(a67, ww, accp[3][3]);
        }
        __syncthreads();
    }

    float4 b4 = *(const float4*)&bo[c0];
#pragma unroll
    for (int rp = 0; rp < 4; rp++) {
        float2 p0 = unpack2(accp[0][rp]);
        float2 p1 = unpack2(accp[1][rp]);
        float2 p2 = unpack2(accp[2][rp]);
        float2 p3 = unpack2(accp[3][rp]);
        int ra = r0 + 2*rp;
        float4 va = make_float4(p0.x + b4.x, p1.x + b4.y, p2.x + b4.z, p3.x + b4.w);
        float4 vb = make_float4(p0.y + b4.x, p1.y + b4.y, p2.y + b4.z, p3.y + b4.w);
        *(float4*)&sW[ra*260 + c0]     = va;
        *(float4*)&sW[(ra+1)*260 + c0] = vb;
    }
    __syncthreads();

    const int lane = t & 31, wid = t >> 5;
    for (int r = wid; r < 32; r += 8) {
        float s = 0.0f;
#pragma unroll
        for (int i = lane; i < GD; i += 32) s += sW[r*260 + i];
#pragma unroll
        for (int o = 16; o >= 1; o >>= 1) s += __shfl_xor_sync(FULLMASK, s, o);
        float mu = s * (1.0f / GD);
        float v = 0.0f;
#pragma unroll
        for (int i = lane; i < GD; i += 32) {
            float d = sW[r*260 + i] - mu;
            v = fmaf(d, d, v);
        }
#pragma unroll
        for (int o = 16; o >= 1; o >>= 1) v += __shfl_xor_sync(FULLMASK, v, o);
        if (lane == 0) { sMu[r] = mu; sRs[r] = rsqrtf(v * (1.0f / GD) + EPSLN); }
    }
    __syncthreads();

    float4 g4 = *(const float4*)&lng[c0];
    float4 be4 = *(const float4*)&lnb[c0];
    float4* out4 = (float4*)out;
#pragma unroll
    for (int r = 0; r < 8; r++) {
        int rr = r0 + r;
        float mu = sMu[rr], rs = sRs[rr];
        float4 v = *(const float4*)&sW[rr*260 + c0];
        v.x = (v.x - mu) * rs * g4.x + be4.x;
        v.y = (v.y - mu) * rs * g4.y + be4.y;
        v.z = (v.z - mu) * rs * g4.z + be4.z;
        v.w = (v.w - mu) * rs * g4.w + be4.w;
        out4[(size_t)(row0 + rr)*64 + tx] = v;
    }
}

// ======================================================================
// launcher — fork/join: pf runs concurrently with bin->knn.
// ======================================================================
extern "C" void kernel_launch(void* const* d_in, const int* in_sizes, int n_in,
                              void* d_out, int out_size)
{
    const float* point_features = (const float*)d_in[0];
    const float* point_coords   = (const float*)d_in[1];
    const float* W_feat         = (const float*)d_in[2];
    const float* b_feat         = (const float*)d_in[3];
    const float* W1             = (const float*)d_in[4];
    const float* b1             = (const float*)d_in[5];
    const float* W2             = (const float*)d_in[6];
    const float* b2             = (const float*)d_in[7];
    const float* W_out          = (const float*)d_in[8];
    const float* b_out          = (const float*)d_in[9];
    const float* ln_g           = (const float*)d_in[10];
    const float* ln_b           = (const float*)d_in[11];
    float* out = (float*)d_out;

    cudaStream_t s1;
    cudaStreamCreateWithFlags(&s1, cudaStreamNonBlocking);
    cudaEvent_t evFork, evJoin;
    cudaEventCreateWithFlags(&evFork, cudaEventDisableTiming);
    cudaEventCreateWithFlags(&evJoin, cudaEventDisableTiming);

    // fork: branch A (pf) on s1
    cudaEventRecord(evFork, 0);
    cudaStreamWaitEvent(s1, evFork, 0);
    pf_kernel<<<NPTS/32, 256, 0, s1>>>(point_features, W_feat, b_feat);
    cudaEventRecord(evJoin, s1);

    // branch B (bin -> knn) on the main (capture) stream
    bin_all_kernel<<<1, 1024>>>(point_coords);
    knn_kernel<<<G/GPB, 256>>>();

    // join: attn needs both pf and knn
    cudaStreamWaitEvent(0, evJoin, 0);
    attn_gather_kernel<<<G/GPB, 256>>>(point_coords, W1, b1, W2, b2);
    outproj_ln_kernel<<<G/32, 256>>>(W_out, b_out, ln_g, ln_b, out);

    cudaEventDestroy(evFork);
    cudaEventDestroy(evJoin);
    cudaStreamDestroy(s1);
}